// round 2
// baseline (speedup 1.0000x reference)
#include <cuda_runtime.h>
#include <math.h>

// Problem constants
#define B_   4
#define S_   2048
#define H_   1024
#define NH_  16
#define D_   64
#define MTOT (B_ * S_)          // 8192 rows for all dense GEMMs

// Scratch (allocation-free rule: __device__ globals)
__device__ float g_Q[(size_t)B_ * NH_ * S_ * D_];   // [b,h,s,d]
__device__ float g_K[(size_t)B_ * NH_ * S_ * D_];
__device__ float g_V[(size_t)B_ * NH_ * S_ * D_];
__device__ float g_AO[(size_t)B_ * S_ * H_];        // [b,s,h*d]

// ---------------------------------------------------------------------------
// Dense GEMM: C = A[M,1024] @ W[1024,1024] + bias
// layout 0: C row-major [M,1024]   (output projection -> d_out)
// layout 1: C permuted to [b,h,s,d] (QKV projections -> g_Q/g_K/g_V)
// 128x128 tile, BK=16, 256 threads, 8x8 register micro-tile.
// ---------------------------------------------------------------------------
__global__ __launch_bounds__(256)
void sgemm_kernel(const float* __restrict__ A, const float* __restrict__ W,
                  const float* __restrict__ bias, float* __restrict__ C,
                  int layout)
{
    const int K = H_, N = H_;
    __shared__ float As[16][128];   // transposed: As[k][m]
    __shared__ float Bs[16][128];   // Bs[k][n]

    const int tid = threadIdx.x;
    const int bm = blockIdx.y * 128;
    const int bn = blockIdx.x * 128;
    const int tr = (tid >> 4) << 3;      // 0..120 step 8
    const int tc = (tid & 15) << 3;

    const int arow = tid >> 2;           // 0..63
    const int acol = (tid & 3) << 2;     // 0,4,8,12
    const int brow = tid >> 5;           // 0..7
    const int bcol = (tid & 31) << 2;    // 0..124 step 4

    float acc[8][8];
#pragma unroll
    for (int i = 0; i < 8; i++)
#pragma unroll
        for (int j = 0; j < 8; j++) acc[i][j] = 0.f;

    for (int k0 = 0; k0 < K; k0 += 16) {
#pragma unroll
        for (int i = 0; i < 2; i++) {
            float4 va = *(const float4*)(A + (size_t)(bm + arow + i * 64) * K + k0 + acol);
            As[acol + 0][arow + i * 64] = va.x;
            As[acol + 1][arow + i * 64] = va.y;
            As[acol + 2][arow + i * 64] = va.z;
            As[acol + 3][arow + i * 64] = va.w;
        }
#pragma unroll
        for (int i = 0; i < 2; i++) {
            *(float4*)&Bs[brow + i * 8][bcol] =
                *(const float4*)(W + (size_t)(k0 + brow + i * 8) * N + bn + bcol);
        }
        __syncthreads();

#pragma unroll
        for (int kk = 0; kk < 16; kk++) {
            float a[8], b[8];
            *(float4*)&a[0] = *(float4*)&As[kk][tr];
            *(float4*)&a[4] = *(float4*)&As[kk][tr + 4];
            *(float4*)&b[0] = *(float4*)&Bs[kk][tc];
            *(float4*)&b[4] = *(float4*)&Bs[kk][tc + 4];
#pragma unroll
            for (int i = 0; i < 8; i++)
#pragma unroll
                for (int j = 0; j < 8; j++)
                    acc[i][j] += a[i] * b[j];
        }
        __syncthreads();
    }

    // epilogue: bias + store
    float bv[8];
    *(float4*)&bv[0] = *(const float4*)(bias + bn + tc);
    *(float4*)&bv[4] = *(const float4*)(bias + bn + tc + 4);

#pragma unroll
    for (int i = 0; i < 8; i++) {
        const int m = bm + tr + i;
#pragma unroll
        for (int jj = 0; jj < 8; jj += 4) {
            float4 v;
            v.x = acc[i][jj + 0] + bv[jj + 0];
            v.y = acc[i][jj + 1] + bv[jj + 1];
            v.z = acc[i][jj + 2] + bv[jj + 2];
            v.w = acc[i][jj + 3] + bv[jj + 3];
            const int n = bn + tc + jj;
            if (layout == 0) {
                *(float4*)(C + (size_t)m * N + n) = v;
            } else {
                const int b = m >> 11;          // /S_
                const int s = m & (S_ - 1);
                const int h = n >> 6;           // /D_
                const int d = n & (D_ - 1);
                *(float4*)(C + ((size_t)(b * NH_ + h) * S_ + s) * D_ + d) = v;
            }
        }
    }
}

// ---------------------------------------------------------------------------
// Flash attention: per block one (b,h) and one 64-row Q tile.
// Br=Bc=64, 256 threads in 16x16 grid, each owns 4x4 of S and 4x4 of O.
// Online softmax (row stats replicated across the 16-lane col group via shfl).
// ---------------------------------------------------------------------------
#define SP 68   // padded smem pitch (floats)

__global__ __launch_bounds__(256)
void attn_kernel()
{
    extern __shared__ float sm[];
    float* Qs = sm;                  // 64 x SP
    float* Ks = sm + 64 * SP;
    float* Vs = sm + 2 * 64 * SP;
    float* Ps = sm + 3 * 64 * SP;

    const int tid = threadIdx.x;
    const int bh  = blockIdx.y;              // b*NH + h
    const int qt  = blockIdx.x * 64;

    const float* Qp = g_Q + (size_t)bh * S_ * D_;
    const float* Kp = g_K + (size_t)bh * S_ * D_;
    const float* Vp = g_V + (size_t)bh * S_ * D_;

    const int r0 = (tid >> 4) * 4;           // 4 owned Q rows
    const int c0 = (tid & 15) * 4;           // 4 owned cols (kv idx / d idx)

    // load Q tile
#pragma unroll
    for (int rep = 0; rep < 4; rep++) {
        const int lin = rep * 256 + tid;
        const int row = lin >> 4, d4 = (lin & 15) * 4;
        *(float4*)&Qs[row * SP + d4] = *(const float4*)(Qp + (size_t)(qt + row) * D_ + d4);
    }

    float m_[4], l_[4], o[4][4];
#pragma unroll
    for (int i = 0; i < 4; i++) {
        m_[i] = -1e30f; l_[i] = 0.f;
#pragma unroll
        for (int j = 0; j < 4; j++) o[i][j] = 0.f;
    }

    for (int kv0 = 0; kv0 < S_; kv0 += 64) {
        // load K,V tiles
#pragma unroll
        for (int rep = 0; rep < 4; rep++) {
            const int lin = rep * 256 + tid;
            const int row = lin >> 4, d4 = (lin & 15) * 4;
            *(float4*)&Ks[row * SP + d4] = *(const float4*)(Kp + (size_t)(kv0 + row) * D_ + d4);
            *(float4*)&Vs[row * SP + d4] = *(const float4*)(Vp + (size_t)(kv0 + row) * D_ + d4);
        }
        __syncthreads();   // K,V (and Q on first iter) visible

        // S = Q K^T (each thread 4x4)
        float s[4][4];
#pragma unroll
        for (int i = 0; i < 4; i++)
#pragma unroll
            for (int j = 0; j < 4; j++) s[i][j] = 0.f;

#pragma unroll
        for (int d = 0; d < 64; d += 4) {
            float qa[4][4], kb[4][4];
#pragma unroll
            for (int i = 0; i < 4; i++)
                *(float4*)qa[i] = *(float4*)&Qs[(r0 + i) * SP + d];
#pragma unroll
            for (int j = 0; j < 4; j++)
                *(float4*)kb[j] = *(float4*)&Ks[(c0 + j) * SP + d];
#pragma unroll
            for (int i = 0; i < 4; i++)
#pragma unroll
                for (int j = 0; j < 4; j++)
#pragma unroll
                    for (int t = 0; t < 4; t++)
                        s[i][j] += qa[i][t] * kb[j][t];
        }

        // scale + online softmax per row
#pragma unroll
        for (int i = 0; i < 4; i++) {
#pragma unroll
            for (int j = 0; j < 4; j++) s[i][j] *= 0.125f;   // 1/sqrt(64)

            float mt = fmaxf(fmaxf(s[i][0], s[i][1]), fmaxf(s[i][2], s[i][3]));
#pragma unroll
            for (int off = 8; off > 0; off >>= 1)
                mt = fmaxf(mt, __shfl_xor_sync(0xffffffffu, mt, off));

            const float mnew = fmaxf(m_[i], mt);
            const float f = __expf(m_[i] - mnew);
            float rs = 0.f;
#pragma unroll
            for (int j = 0; j < 4; j++) {
                const float p = __expf(s[i][j] - mnew);
                s[i][j] = p;
                rs += p;
            }
#pragma unroll
            for (int off = 8; off > 0; off >>= 1)
                rs += __shfl_xor_sync(0xffffffffu, rs, off);

            l_[i] = l_[i] * f + rs;
            m_[i] = mnew;
#pragma unroll
            for (int j = 0; j < 4; j++) o[i][j] *= f;
        }

        // stage P to smem for the PV GEMM
#pragma unroll
        for (int i = 0; i < 4; i++) {
            float4 pv = make_float4(s[i][0], s[i][1], s[i][2], s[i][3]);
            *(float4*)&Ps[(r0 + i) * SP + c0] = pv;
        }
        __syncthreads();   // P visible to all

        // O += P @ V
#pragma unroll
        for (int kv = 0; kv < 64; kv += 4) {
            float pa[4][4], vb[4][4];
#pragma unroll
            for (int i = 0; i < 4; i++)
                *(float4*)pa[i] = *(float4*)&Ps[(r0 + i) * SP + kv];
#pragma unroll
            for (int t = 0; t < 4; t++)
                *(float4*)vb[t] = *(float4*)&Vs[(kv + t) * SP + c0];
#pragma unroll
            for (int i = 0; i < 4; i++)
#pragma unroll
                for (int j = 0; j < 4; j++)
#pragma unroll
                    for (int t = 0; t < 4; t++)
                        o[i][j] += pa[i][t] * vb[t][j];
        }
        __syncthreads();   // done with Ks/Vs/Ps before next iter overwrites
    }

    // epilogue: normalize, write to [b, s, h*64+d]
    const int b = bh >> 4, h = bh & 15;
    float* AO = g_AO + (size_t)(b * S_ + qt) * H_ + h * D_;
#pragma unroll
    for (int i = 0; i < 4; i++) {
        const float invl = 1.0f / l_[i];
        float4 v;
        v.x = o[i][0] * invl;
        v.y = o[i][1] * invl;
        v.z = o[i][2] * invl;
        v.w = o[i][3] * invl;
        *(float4*)(AO + (size_t)(r0 + i) * H_ + c0) = v;
    }
}

// ---------------------------------------------------------------------------
// kernel_launch: 5 launches, graph-capturable, allocation-free.
// ---------------------------------------------------------------------------
extern "C" void kernel_launch(void* const* d_in, const int* in_sizes, int n_in,
                              void* d_out, int out_size)
{
    const float* q  = (const float*)d_in[0];
    const float* k  = (const float*)d_in[1];
    const float* v  = (const float*)d_in[2];
    const float* wq = (const float*)d_in[3];
    const float* bq = (const float*)d_in[4];
    const float* wk = (const float*)d_in[5];
    const float* bk = (const float*)d_in[6];
    const float* wv = (const float*)d_in[7];
    const float* bv = (const float*)d_in[8];
    const float* wo = (const float*)d_in[9];
    const float* bo = (const float*)d_in[10];
    float* out = (float*)d_out;

    float *Qp, *Kp, *Vp, *AOp;
    cudaGetSymbolAddress((void**)&Qp,  g_Q);
    cudaGetSymbolAddress((void**)&Kp,  g_K);
    cudaGetSymbolAddress((void**)&Vp,  g_V);
    cudaGetSymbolAddress((void**)&AOp, g_AO);

    const int attn_smem = 4 * 64 * SP * (int)sizeof(float);   // 69,632 B
    cudaFuncSetAttribute(attn_kernel, cudaFuncAttributeMaxDynamicSharedMemorySize, attn_smem);

    dim3 gg(8, 64), bb(256);
    sgemm_kernel<<<gg, bb>>>(q, wq, bq, Qp, 1);
    sgemm_kernel<<<gg, bb>>>(k, wk, bk, Kp, 1);
    sgemm_kernel<<<gg, bb>>>(v, wv, bv, Vp, 1);
    attn_kernel<<<dim3(32, 64), 256, attn_smem>>>();
    sgemm_kernel<<<gg, bb>>>(AOp, wo, bo, out, 0);
}

// round 4
// speedup vs baseline: 1.2623x; 1.2623x over previous
#include <cuda_runtime.h>
#include <math.h>

// Problem constants
#define B_   4
#define S_   2048
#define H_   1024
#define NH_  16
#define D_   64

// Scratch (allocation-free rule: __device__ globals)
__device__ float g_Q[(size_t)B_ * NH_ * S_ * D_];   // [b,h,s,d]
__device__ float g_K[(size_t)B_ * NH_ * S_ * D_];
__device__ float g_V[(size_t)B_ * NH_ * S_ * D_];
__device__ float g_AO[(size_t)B_ * S_ * H_];        // [b,s,h*d]

typedef unsigned long long u64;

__device__ __forceinline__ float lo32(u64 x) { return __uint_as_float((unsigned)x); }
__device__ __forceinline__ float hi32(u64 x) { return __uint_as_float((unsigned)(x >> 32)); }

__device__ __forceinline__ void fma2(u64& acc, u64 a, u64 b) {
    asm volatile("fma.rn.f32x2 %0, %1, %2, %0;" : "+l"(acc) : "l"(a), "l"(b));
}

// ---------------------------------------------------------------------------
// Dense GEMM: C = A[M,1024] @ W[1024,1024] + bias, fp32 with packed FFMA2.
// 128x128 tile, BK=16, 256 threads, 8x8 micro-tile (acc pairs along n).
// As2: [k][2m] A duplicated per element  -> a-dup pairs load as b64 (broadcast)
// Bs:  [k][n]  with +4-float pad every 32 -> conflict-free strided loads
// ---------------------------------------------------------------------------
#define AP2 258            // As2 pitch in floats (2*128 + 2)
#define BP  140            // Bs pitch in floats (128 + 3*4 pad)
__device__ __forceinline__ int bpad(int c) { return c + ((c >> 5) << 2); }

__global__ __launch_bounds__(256, 2)
void sgemm_kernel(const float* __restrict__ A, const float* __restrict__ W,
                  const float* __restrict__ bias, float* __restrict__ C,
                  int layout)
{
    const int K = H_, N = H_;
    __shared__ float As2[16 * AP2];
    __shared__ float Bs[16 * BP];

    const int tid = threadIdx.x;
    const int bm = blockIdx.y * 128;
    const int bn = blockIdx.x * 128;
    const int tr = (tid >> 4) << 3;      // 0..120 step 8
    const int tc = (tid & 15) << 3;

    const int arow = tid >> 2;           // 0..63
    const int acol = (tid & 3) << 2;     // 0,4,8,12
    const int brow = tid >> 5;           // 0..7
    const int bcol = (tid & 31) << 2;    // 0..124 step 4

    u64 acc2[8][4];
#pragma unroll
    for (int i = 0; i < 8; i++)
#pragma unroll
        for (int j = 0; j < 4; j++) acc2[i][j] = 0ull;

    for (int k0 = 0; k0 < K; k0 += 16) {
        // A tile -> As2 [k][2m], duplicated
#pragma unroll
        for (int i = 0; i < 2; i++) {
            float4 va = *(const float4*)(A + (size_t)(bm + arow + i * 64) * K + k0 + acol);
            const int m2 = 2 * (arow + i * 64);
            *(float2*)&As2[(acol + 0) * AP2 + m2] = make_float2(va.x, va.x);
            *(float2*)&As2[(acol + 1) * AP2 + m2] = make_float2(va.y, va.y);
            *(float2*)&As2[(acol + 2) * AP2 + m2] = make_float2(va.z, va.z);
            *(float2*)&As2[(acol + 3) * AP2 + m2] = make_float2(va.w, va.w);
        }
        // W tile -> Bs [k][n] padded
#pragma unroll
        for (int i = 0; i < 2; i++) {
            *(float4*)&Bs[(brow + i * 8) * BP + bpad(bcol)] =
                *(const float4*)(W + (size_t)(k0 + brow + i * 8) * N + bn + bcol);
        }
        __syncthreads();

#pragma unroll
        for (int kk = 0; kk < 16; kk++) {
            u64 ad[8], bp[4];
            const float* arow_p = &As2[kk * AP2 + 2 * tr];
            const float* brow_p = &Bs[kk * BP + bpad(tc)];
#pragma unroll
            for (int i = 0; i < 8; i++) ad[i] = *(const u64*)(arow_p + 2 * i);
#pragma unroll
            for (int j = 0; j < 4; j++) bp[j] = *(const u64*)(brow_p + 2 * j);
#pragma unroll
            for (int i = 0; i < 8; i++)
#pragma unroll
                for (int j = 0; j < 4; j++)
                    fma2(acc2[i][j], ad[i], bp[j]);
        }
        __syncthreads();
    }

    // epilogue: bias + store
    float bv[8];
    *(float4*)&bv[0] = *(const float4*)(bias + bn + tc);
    *(float4*)&bv[4] = *(const float4*)(bias + bn + tc + 4);

#pragma unroll
    for (int i = 0; i < 8; i++) {
        const int m = bm + tr + i;
#pragma unroll
        for (int jj = 0; jj < 2; jj++) {
            float4 v;
            v.x = lo32(acc2[i][2 * jj + 0]) + bv[4 * jj + 0];
            v.y = hi32(acc2[i][2 * jj + 0]) + bv[4 * jj + 1];
            v.z = lo32(acc2[i][2 * jj + 1]) + bv[4 * jj + 2];
            v.w = hi32(acc2[i][2 * jj + 1]) + bv[4 * jj + 3];
            const int n = bn + tc + 4 * jj;
            if (layout == 0) {
                *(float4*)(C + (size_t)m * N + n) = v;
            } else {
                const int b = m >> 11;          // /S_
                const int s = m & (S_ - 1);
                const int h = n >> 6;           // /D_
                const int d = n & (D_ - 1);
                *(float4*)(C + ((size_t)(b * NH_ + h) * S_ + s) * D_ + d) = v;
            }
        }
    }
}

// ---------------------------------------------------------------------------
// Flash attention, Br=Bc=64, 256 threads (16x16), 4x4 micro.
// smem XOR-swizzled: float4-group index xored with (row>>2)&7 -> conflict-free
// for row-strided (kb, vb) and col-spread (P-store) patterns.
// QK^T uses packed FFMA2 paired along d (both pairs free from consecutive smem).
// ---------------------------------------------------------------------------
#define AP 68   // pitch (floats)

// offset of float4-group c4 in row r
__device__ __forceinline__ int swz4(int r, int c4) {
    return r * AP + (((c4 ^ ((r >> 2) & 7))) << 2);
}

__global__ __launch_bounds__(256, 2)
void attn_kernel()
{
    extern __shared__ float sm[];
    float* Qs = sm;                  // 64 x AP (pre-scaled by 1/8)
    float* Ks = sm + 64 * AP;
    float* Vs = sm + 2 * 64 * AP;
    float* Ps = sm + 3 * 64 * AP;

    const int tid = threadIdx.x;
    const int bh  = blockIdx.y;              // b*NH + h
    const int qt  = blockIdx.x * 64;

    const float* Qp = g_Q + (size_t)bh * S_ * D_;
    const float* Kp = g_K + (size_t)bh * S_ * D_;
    const float* Vp = g_V + (size_t)bh * S_ * D_;

    const int r0 = (tid >> 4) * 4;           // 4 owned Q rows
    const int c0 = (tid & 15) * 4;           // 4 owned cols (kv idx / d idx)
    const int cg = tid & 15;                 // col-group index (= c0>>2)

    // load Q tile (fold 1/sqrt(64) = 0.125 into Q)
#pragma unroll
    for (int rep = 0; rep < 4; rep++) {
        const int lin = rep * 256 + tid;
        const int row = lin >> 4, d4 = lin & 15;
        float4 v = *(const float4*)(Qp + (size_t)(qt + row) * D_ + 4 * d4);
        v.x *= 0.125f; v.y *= 0.125f; v.z *= 0.125f; v.w *= 0.125f;
        *(float4*)&Qs[swz4(row, d4)] = v;
    }

    float m_[4], l_[4], o[4][4];
#pragma unroll
    for (int i = 0; i < 4; i++) {
        m_[i] = -1e30f; l_[i] = 0.f;
#pragma unroll
        for (int j = 0; j < 4; j++) o[i][j] = 0.f;
    }

    for (int kv0 = 0; kv0 < S_; kv0 += 64) {
        // load K,V tiles (swizzled)
#pragma unroll
        for (int rep = 0; rep < 4; rep++) {
            const int lin = rep * 256 + tid;
            const int row = lin >> 4, d4 = lin & 15;
            const int off = swz4(row, d4);
            *(float4*)&Ks[off] = *(const float4*)(Kp + (size_t)(kv0 + row) * D_ + 4 * d4);
            *(float4*)&Vs[off] = *(const float4*)(Vp + (size_t)(kv0 + row) * D_ + 4 * d4);
        }
        __syncthreads();

        // S = Q K^T, packed along d: s2 accumulates (even-d, odd-d) halves
        u64 s2[4][4];
#pragma unroll
        for (int i = 0; i < 4; i++)
#pragma unroll
            for (int j = 0; j < 4; j++) s2[i][j] = 0ull;

#pragma unroll
        for (int d4 = 0; d4 < 16; d4++) {
            u64 qa[4][2], kb[4][2];
#pragma unroll
            for (int i = 0; i < 4; i++) {
                const float* p = &Qs[swz4(r0 + i, d4)];
                qa[i][0] = *(const u64*)p;
                qa[i][1] = *(const u64*)(p + 2);
            }
#pragma unroll
            for (int j = 0; j < 4; j++) {
                const float* p = &Ks[swz4(c0 + j, d4)];
                kb[j][0] = *(const u64*)p;
                kb[j][1] = *(const u64*)(p + 2);
            }
#pragma unroll
            for (int i = 0; i < 4; i++)
#pragma unroll
                for (int j = 0; j < 4; j++) {
                    fma2(s2[i][j], qa[i][0], kb[j][0]);
                    fma2(s2[i][j], qa[i][1], kb[j][1]);
                }
        }

        // combine halves + online softmax per row
        float s[4][4];
#pragma unroll
        for (int i = 0; i < 4; i++) {
#pragma unroll
            for (int j = 0; j < 4; j++)
                s[i][j] = lo32(s2[i][j]) + hi32(s2[i][j]);

            float mt = fmaxf(fmaxf(s[i][0], s[i][1]), fmaxf(s[i][2], s[i][3]));
#pragma unroll
            for (int off = 8; off > 0; off >>= 1)
                mt = fmaxf(mt, __shfl_xor_sync(0xffffffffu, mt, off));

            const float mnew = fmaxf(m_[i], mt);
            const float f = __expf(m_[i] - mnew);
            float rs = 0.f;
#pragma unroll
            for (int j = 0; j < 4; j++) {
                const float p = __expf(s[i][j] - mnew);
                s[i][j] = p;
                rs += p;
            }
#pragma unroll
            for (int off = 8; off > 0; off >>= 1)
                rs += __shfl_xor_sync(0xffffffffu, rs, off);

            l_[i] = l_[i] * f + rs;
            m_[i] = mnew;
#pragma unroll
            for (int j = 0; j < 4; j++) o[i][j] *= f;
        }

        // stage P to smem (swizzled)
#pragma unroll
        for (int i = 0; i < 4; i++) {
            float4 pv = make_float4(s[i][0], s[i][1], s[i][2], s[i][3]);
            *(float4*)&Ps[swz4(r0 + i, cg)] = pv;
        }
        __syncthreads();

        // O += P @ V  (scalar FFMA; pa broadcast, vb conflict-free via swizzle)
#pragma unroll
        for (int kv4 = 0; kv4 < 16; kv4++) {
            float4 pa[4], vb[4];
#pragma unroll
            for (int i = 0; i < 4; i++)
                pa[i] = *(const float4*)&Ps[swz4(r0 + i, kv4)];
#pragma unroll
            for (int t = 0; t < 4; t++)
                vb[t] = *(const float4*)&Vs[swz4(4 * kv4 + t, cg)];
#pragma unroll
            for (int i = 0; i < 4; i++) {
                o[i][0] += pa[i].x * vb[0].x + pa[i].y * vb[1].x + pa[i].z * vb[2].x + pa[i].w * vb[3].x;
                o[i][1] += pa[i].x * vb[0].y + pa[i].y * vb[1].y + pa[i].z * vb[2].y + pa[i].w * vb[3].y;
                o[i][2] += pa[i].x * vb[0].z + pa[i].y * vb[1].z + pa[i].z * vb[2].z + pa[i].w * vb[3].z;
                o[i][3] += pa[i].x * vb[0].w + pa[i].y * vb[1].w + pa[i].z * vb[2].w + pa[i].w * vb[3].w;
            }
        }
        __syncthreads();   // done with Ks/Vs/Ps before next iter overwrites
    }

    // epilogue: normalize, write to [b, s, h*64+d]
    const int b = bh >> 4, h = bh & 15;
    float* AO = g_AO + (size_t)(b * S_ + qt) * H_ + h * D_;
#pragma unroll
    for (int i = 0; i < 4; i++) {
        const float invl = 1.0f / l_[i];
        float4 v;
        v.x = o[i][0] * invl;
        v.y = o[i][1] * invl;
        v.z = o[i][2] * invl;
        v.w = o[i][3] * invl;
        *(float4*)(AO + (size_t)(r0 + i) * H_ + c0) = v;
    }
}

// ---------------------------------------------------------------------------
// kernel_launch: 5 launches, graph-capturable, allocation-free.
// ---------------------------------------------------------------------------
extern "C" void kernel_launch(void* const* d_in, const int* in_sizes, int n_in,
                              void* d_out, int out_size)
{
    const float* q  = (const float*)d_in[0];
    const float* k  = (const float*)d_in[1];
    const float* v  = (const float*)d_in[2];
    const float* wq = (const float*)d_in[3];
    const float* bq = (const float*)d_in[4];
    const float* wk = (const float*)d_in[5];
    const float* bk = (const float*)d_in[6];
    const float* wv = (const float*)d_in[7];
    const float* bv = (const float*)d_in[8];
    const float* wo = (const float*)d_in[9];
    const float* bo = (const float*)d_in[10];
    float* out = (float*)d_out;

    float *Qp, *Kp, *Vp, *AOp;
    cudaGetSymbolAddress((void**)&Qp,  g_Q);
    cudaGetSymbolAddress((void**)&Kp,  g_K);
    cudaGetSymbolAddress((void**)&Vp,  g_V);
    cudaGetSymbolAddress((void**)&AOp, g_AO);

    const int attn_smem = 4 * 64 * AP * (int)sizeof(float);   // 69,632 B
    cudaFuncSetAttribute(attn_kernel, cudaFuncAttributeMaxDynamicSharedMemorySize, attn_smem);

    dim3 gg(8, 64), bb(256);
    sgemm_kernel<<<gg, bb>>>(q, wq, bq, Qp, 1);
    sgemm_kernel<<<gg, bb>>>(k, wk, bk, Kp, 1);
    sgemm_kernel<<<gg, bb>>>(v, wv, bv, Vp, 1);
    attn_kernel<<<dim3(32, 64), 256, attn_smem>>>();
    sgemm_kernel<<<gg, bb>>>(AOp, wo, bo, out, 0);
}

// round 8
// speedup vs baseline: 1.6267x; 1.2886x over previous
#include <cuda_runtime.h>
#include <cuda_bf16.h>
#include <math.h>

// Problem constants
#define B_   4
#define S_   2048
#define H_   1024
#define NH_  16
#define D_   64
#define NACT (B_ * S_ * H_)      // 8,388,608 activation elements
#define NWGT (H_ * H_)           // 1,048,576 weight elements

// ---------------------------------------------------------------------------
// Scratch (__device__ globals; allocation-free rule)
// ---------------------------------------------------------------------------
__device__ float g_Q[(size_t)B_ * NH_ * S_ * D_];   // [b,h,s,d] fp32
__device__ float g_K[(size_t)B_ * NH_ * S_ * D_];
__device__ float g_V[(size_t)B_ * NH_ * S_ * D_];
__device__ float g_AO[(size_t)B_ * S_ * H_];        // [b,s,h*d] fp32

// bf16 hi/lo splits (AO split aliases the Q split: Q's is dead after GEMM 1)
__device__ __nv_bfloat16 g_qhi[NACT], g_qlo[NACT];
__device__ __nv_bfloat16 g_khi[NACT], g_klo[NACT];
__device__ __nv_bfloat16 g_vhi[NACT], g_vlo[NACT];
__device__ __nv_bfloat16 g_wqhi[NWGT], g_wqlo[NWGT];
__device__ __nv_bfloat16 g_wkhi[NWGT], g_wklo[NWGT];
__device__ __nv_bfloat16 g_wvhi[NWGT], g_wvlo[NWGT];
__device__ __nv_bfloat16 g_wohi[NWGT], g_wolo[NWGT];

typedef unsigned long long u64;
typedef unsigned int u32;

__device__ __forceinline__ float lo32(u64 x) { return __uint_as_float((unsigned)x); }
__device__ __forceinline__ float hi32(u64 x) { return __uint_as_float((unsigned)(x >> 32)); }
__device__ __forceinline__ void fma2(u64& acc, u64 a, u64 b) {
    asm volatile("fma.rn.f32x2 %0, %1, %2, %0;" : "+l"(acc) : "l"(a), "l"(b));
}
__device__ __forceinline__ u32 smem_u32(const void* p) {
    return (u32)__cvta_generic_to_shared(p);
}
__device__ __forceinline__ void ldsm_x4(u32& r0, u32& r1, u32& r2, u32& r3, u32 addr) {
    asm volatile("ldmatrix.sync.aligned.m8n8.x4.shared.b16 {%0,%1,%2,%3}, [%4];"
                 : "=r"(r0), "=r"(r1), "=r"(r2), "=r"(r3) : "r"(addr));
}
__device__ __forceinline__ void ldsm_x4_t(u32& r0, u32& r1, u32& r2, u32& r3, u32 addr) {
    asm volatile("ldmatrix.sync.aligned.m8n8.x4.trans.shared.b16 {%0,%1,%2,%3}, [%4];"
                 : "=r"(r0), "=r"(r1), "=r"(r2), "=r"(r3) : "r"(addr));
}
__device__ __forceinline__ void mma16816(float& d0, float& d1, float& d2, float& d3,
                                         u32 a0, u32 a1, u32 a2, u32 a3,
                                         u32 b0, u32 b1) {
    asm volatile(
        "mma.sync.aligned.m16n8k16.row.col.f32.bf16.bf16.f32 "
        "{%0,%1,%2,%3}, {%4,%5,%6,%7}, {%8,%9}, {%0,%1,%2,%3};"
        : "+f"(d0), "+f"(d1), "+f"(d2), "+f"(d3)
        : "r"(a0), "r"(a1), "r"(a2), "r"(a3), "r"(b0), "r"(b1));
}

// ---------------------------------------------------------------------------
// fp32 -> bf16 (hi, lo) split.  x ~= hi + lo to ~17 mantissa bits.
// ---------------------------------------------------------------------------
__global__ __launch_bounds__(256)
void convert_kernel(const float* __restrict__ x,
                    __nv_bfloat16* __restrict__ hi,
                    __nv_bfloat16* __restrict__ lo, int n4)
{
    int i = blockIdx.x * blockDim.x + threadIdx.x;
    if (i >= n4) return;
    float4 v = *(const float4*)(x + 4 * (size_t)i);
    __nv_bfloat16 h0 = __float2bfloat16_rn(v.x);
    __nv_bfloat16 h1 = __float2bfloat16_rn(v.y);
    __nv_bfloat16 h2 = __float2bfloat16_rn(v.z);
    __nv_bfloat16 h3 = __float2bfloat16_rn(v.w);
    __nv_bfloat16 l0 = __float2bfloat16_rn(v.x - __bfloat162float(h0));
    __nv_bfloat16 l1 = __float2bfloat16_rn(v.y - __bfloat162float(h1));
    __nv_bfloat16 l2 = __float2bfloat16_rn(v.z - __bfloat162float(h2));
    __nv_bfloat16 l3 = __float2bfloat16_rn(v.w - __bfloat162float(h3));
    __nv_bfloat162* hp = (__nv_bfloat162*)(hi + 4 * (size_t)i);
    __nv_bfloat162* lp = (__nv_bfloat162*)(lo + 4 * (size_t)i);
    hp[0] = __nv_bfloat162(h0, h1); hp[1] = __nv_bfloat162(h2, h3);
    lp[0] = __nv_bfloat162(l0, l1); lp[1] = __nv_bfloat162(l2, l3);
}

// ---------------------------------------------------------------------------
// Tensor-core GEMM: C = A[M,1024] @ W[1024,1024] + bias  via bf16x3 mma.sync.
// Block tile 128(M) x 64(N), BK=32, 256 threads = 8 warps (4 M x 2 N),
// warp tile 32x32: 2 m16-tiles x 4 n8-tiles, 3 passes (hh, hl, lh).
// A smem [128][BK] pitch 40 bf16; W smem [BK][64] pitch 72 bf16 (LDSM-safe).
// ---------------------------------------------------------------------------
#define APIT 40
#define BPIT 72

__global__ __launch_bounds__(256)
void mma_gemm_kernel(const __nv_bfloat16* __restrict__ Ahi_g,
                     const __nv_bfloat16* __restrict__ Alo_g,
                     const __nv_bfloat16* __restrict__ Whi_g,
                     const __nv_bfloat16* __restrict__ Wlo_g,
                     const float* __restrict__ bias,
                     float* __restrict__ C, int layout)
{
    __shared__ __nv_bfloat16 sAhi[128 * APIT], sAlo[128 * APIT];
    __shared__ __nv_bfloat16 sBhi[32 * BPIT],  sBlo[32 * BPIT];

    const int tid = threadIdx.x;
    const int lane = tid & 31;
    const int wid = tid >> 5;
    const int wm = wid & 3;            // warp m index (0..3)
    const int wn = wid >> 2;           // warp n index (0..1)
    const int bm = blockIdx.y * 128;
    const int bn = blockIdx.x * 64;

    // gmem->smem assignments
    const int a_row = tid >> 1;                 // 0..127
    const int a_chk = (tid & 1) << 4;           // 0 or 16 (bf16 elements)
    const int b_row = tid >> 3;                 // 0..31
    const int b_chk = (tid & 7) << 3;           // 0..56 step 8 (bf16)

    // LDSM source addresses (per k16 step s, add s*16*2 for A / s*16*BPIT*2 for B)
    const int a_r = (lane & 15);
    const int a_k = (lane >> 4) << 3;
    const u32 sAhi_b = smem_u32(sAhi), sAlo_b = smem_u32(sAlo);
    const u32 sBhi_b = smem_u32(sBhi), sBlo_b = smem_u32(sBlo);
    // A tile base for this warp's m-tiles: rows wm*32 + mi*16
    u32 aAddr[2];
#pragma unroll
    for (int mi = 0; mi < 2; mi++)
        aAddr[mi] = ((wm * 32 + mi * 16 + a_r) * APIT + a_k) * 2;
    // B: rows k (0..31), cols wn*32 + nt*16 + ((lane>>4)<<3)
    const int b_k = (lane & 15);
    u32 bAddr[2];
#pragma unroll
    for (int nt = 0; nt < 2; nt++)
        bAddr[nt] = (b_k * BPIT + wn * 32 + nt * 16 + ((lane >> 4) << 3)) * 2;

    float acc[2][4][4];
#pragma unroll
    for (int mi = 0; mi < 2; mi++)
#pragma unroll
        for (int ni = 0; ni < 4; ni++)
#pragma unroll
            for (int c = 0; c < 4; c++) acc[mi][ni][c] = 0.f;

    for (int k0 = 0; k0 < H_; k0 += 32) {
        // load A tiles (hi & lo): each thread covers 16 bf16 per matrix
        // (a uint4 is 8 bf16 -> TWO uint4 loads per thread per matrix)
        {
            const size_t gofs = (size_t)(bm + a_row) * H_ + k0 + a_chk;
            const int sofs = a_row * APIT + a_chk;
            *(uint4*)&sAhi[sofs]     = *(const uint4*)(Ahi_g + gofs);
            *(uint4*)&sAhi[sofs + 8] = *(const uint4*)(Ahi_g + gofs + 8);
            *(uint4*)&sAlo[sofs]     = *(const uint4*)(Alo_g + gofs);
            *(uint4*)&sAlo[sofs + 8] = *(const uint4*)(Alo_g + gofs + 8);
        }
        // load W tiles (256 thr x 8 bf16 = 2048 = 32x64, exactly covers tile)
        {
            const size_t gofs = (size_t)(k0 + b_row) * H_ + bn + b_chk;
            const int sofs = b_row * BPIT + b_chk;
            *(uint4*)&sBhi[sofs] = *(const uint4*)(Whi_g + gofs);
            *(uint4*)&sBlo[sofs] = *(const uint4*)(Wlo_g + gofs);
        }
        __syncthreads();

#pragma unroll
        for (int s = 0; s < 2; s++) {
            u32 ah[2][4], al[2][4];
#pragma unroll
            for (int mi = 0; mi < 2; mi++) {
                ldsm_x4(ah[mi][0], ah[mi][1], ah[mi][2], ah[mi][3],
                        sAhi_b + aAddr[mi] + s * 32);
                ldsm_x4(al[mi][0], al[mi][1], al[mi][2], al[mi][3],
                        sAlo_b + aAddr[mi] + s * 32);
            }
            u32 bh[4][2], bl[4][2];
#pragma unroll
            for (int nt = 0; nt < 2; nt++) {
                u32 r0, r1, r2, r3;
                ldsm_x4_t(r0, r1, r2, r3, sBhi_b + bAddr[nt] + s * 16 * BPIT * 2);
                bh[nt * 2 + 0][0] = r0; bh[nt * 2 + 0][1] = r1;
                bh[nt * 2 + 1][0] = r2; bh[nt * 2 + 1][1] = r3;
                ldsm_x4_t(r0, r1, r2, r3, sBlo_b + bAddr[nt] + s * 16 * BPIT * 2);
                bl[nt * 2 + 0][0] = r0; bl[nt * 2 + 0][1] = r1;
                bl[nt * 2 + 1][0] = r2; bl[nt * 2 + 1][1] = r3;
            }
#pragma unroll
            for (int mi = 0; mi < 2; mi++)
#pragma unroll
                for (int ni = 0; ni < 4; ni++) {
                    float* d = acc[mi][ni];
                    mma16816(d[0], d[1], d[2], d[3],
                             ah[mi][0], ah[mi][1], ah[mi][2], ah[mi][3],
                             bh[ni][0], bh[ni][1]);
                    mma16816(d[0], d[1], d[2], d[3],
                             ah[mi][0], ah[mi][1], ah[mi][2], ah[mi][3],
                             bl[ni][0], bl[ni][1]);
                    mma16816(d[0], d[1], d[2], d[3],
                             al[mi][0], al[mi][1], al[mi][2], al[mi][3],
                             bh[ni][0], bh[ni][1]);
                }
        }
        __syncthreads();
    }

    // epilogue: bias + store (fragment: c0,c1 -> row g, cols c,c+1; c2,c3 -> row g+8)
    const int gm0 = bm + wm * 32 + (lane >> 2);
    const int gn_base = bn + wn * 32 + 2 * (lane & 3);
#pragma unroll
    for (int ni = 0; ni < 4; ni++) {
        const int n = gn_base + ni * 8;
        const float2 bv = *(const float2*)(bias + n);
#pragma unroll
        for (int mi = 0; mi < 2; mi++) {
#pragma unroll
            for (int half = 0; half < 2; half++) {
                const int m = gm0 + mi * 16 + half * 8;
                float2 v;
                v.x = acc[mi][ni][2 * half + 0] + bv.x;
                v.y = acc[mi][ni][2 * half + 1] + bv.y;
                if (layout == 0) {
                    *(float2*)(C + (size_t)m * H_ + n) = v;
                } else {
                    const int b = m >> 11;
                    const int s = m & (S_ - 1);
                    const int h = n >> 6;
                    const int d = n & (D_ - 1);
                    *(float2*)(C + ((size_t)(b * NH_ + h) * S_ + s) * D_ + d) = v;
                }
            }
        }
    }
}

// ---------------------------------------------------------------------------
// Flash attention (unchanged): Br=Bc=64, 256 thr, swizzled smem, FFMA2 QK.
// ---------------------------------------------------------------------------
#define AP 68   // pitch (floats)

__device__ __forceinline__ int swz4(int r, int c4) {
    return r * AP + (((c4 ^ ((r >> 2) & 7))) << 2);
}

__global__ __launch_bounds__(256, 2)
void attn_kernel()
{
    extern __shared__ float sm[];
    float* Qs = sm;
    float* Ks = sm + 64 * AP;
    float* Vs = sm + 2 * 64 * AP;
    float* Ps = sm + 3 * 64 * AP;

    const int tid = threadIdx.x;
    const int bh  = blockIdx.y;
    const int qt  = blockIdx.x * 64;

    const float* Qp = g_Q + (size_t)bh * S_ * D_;
    const float* Kp = g_K + (size_t)bh * S_ * D_;
    const float* Vp = g_V + (size_t)bh * S_ * D_;

    const int r0 = (tid >> 4) * 4;
    const int c0 = (tid & 15) * 4;
    const int cg = tid & 15;

#pragma unroll
    for (int rep = 0; rep < 4; rep++) {
        const int lin = rep * 256 + tid;
        const int row = lin >> 4, d4 = lin & 15;
        float4 v = *(const float4*)(Qp + (size_t)(qt + row) * D_ + 4 * d4);
        v.x *= 0.125f; v.y *= 0.125f; v.z *= 0.125f; v.w *= 0.125f;
        *(float4*)&Qs[swz4(row, d4)] = v;
    }

    float m_[4], l_[4], o[4][4];
#pragma unroll
    for (int i = 0; i < 4; i++) {
        m_[i] = -1e30f; l_[i] = 0.f;
#pragma unroll
        for (int j = 0; j < 4; j++) o[i][j] = 0.f;
    }

    for (int kv0 = 0; kv0 < S_; kv0 += 64) {
#pragma unroll
        for (int rep = 0; rep < 4; rep++) {
            const int lin = rep * 256 + tid;
            const int row = lin >> 4, d4 = lin & 15;
            const int off = swz4(row, d4);
            *(float4*)&Ks[off] = *(const float4*)(Kp + (size_t)(kv0 + row) * D_ + 4 * d4);
            *(float4*)&Vs[off] = *(const float4*)(Vp + (size_t)(kv0 + row) * D_ + 4 * d4);
        }
        __syncthreads();

        u64 s2[4][4];
#pragma unroll
        for (int i = 0; i < 4; i++)
#pragma unroll
            for (int j = 0; j < 4; j++) s2[i][j] = 0ull;

#pragma unroll
        for (int d4 = 0; d4 < 16; d4++) {
            u64 qa[4][2], kb[4][2];
#pragma unroll
            for (int i = 0; i < 4; i++) {
                const float* p = &Qs[swz4(r0 + i, d4)];
                qa[i][0] = *(const u64*)p;
                qa[i][1] = *(const u64*)(p + 2);
            }
#pragma unroll
            for (int j = 0; j < 4; j++) {
                const float* p = &Ks[swz4(c0 + j, d4)];
                kb[j][0] = *(const u64*)p;
                kb[j][1] = *(const u64*)(p + 2);
            }
#pragma unroll
            for (int i = 0; i < 4; i++)
#pragma unroll
                for (int j = 0; j < 4; j++) {
                    fma2(s2[i][j], qa[i][0], kb[j][0]);
                    fma2(s2[i][j], qa[i][1], kb[j][1]);
                }
        }

        float s[4][4];
#pragma unroll
        for (int i = 0; i < 4; i++) {
#pragma unroll
            for (int j = 0; j < 4; j++)
                s[i][j] = lo32(s2[i][j]) + hi32(s2[i][j]);

            float mt = fmaxf(fmaxf(s[i][0], s[i][1]), fmaxf(s[i][2], s[i][3]));
#pragma unroll
            for (int off = 8; off > 0; off >>= 1)
                mt = fmaxf(mt, __shfl_xor_sync(0xffffffffu, mt, off));

            const float mnew = fmaxf(m_[i], mt);
            const float f = __expf(m_[i] - mnew);
            float rs = 0.f;
#pragma unroll
            for (int j = 0; j < 4; j++) {
                const float p = __expf(s[i][j] - mnew);
                s[i][j] = p;
                rs += p;
            }
#pragma unroll
            for (int off = 8; off > 0; off >>= 1)
                rs += __shfl_xor_sync(0xffffffffu, rs, off);

            l_[i] = l_[i] * f + rs;
            m_[i] = mnew;
#pragma unroll
            for (int j = 0; j < 4; j++) o[i][j] *= f;
        }

#pragma unroll
        for (int i = 0; i < 4; i++) {
            float4 pv = make_float4(s[i][0], s[i][1], s[i][2], s[i][3]);
            *(float4*)&Ps[swz4(r0 + i, cg)] = pv;
        }
        __syncthreads();

#pragma unroll
        for (int kv4 = 0; kv4 < 16; kv4++) {
            float4 pa[4], vb[4];
#pragma unroll
            for (int i = 0; i < 4; i++)
                pa[i] = *(const float4*)&Ps[swz4(r0 + i, kv4)];
#pragma unroll
            for (int t = 0; t < 4; t++)
                vb[t] = *(const float4*)&Vs[swz4(4 * kv4 + t, cg)];
#pragma unroll
            for (int i = 0; i < 4; i++) {
                o[i][0] += pa[i].x * vb[0].x + pa[i].y * vb[1].x + pa[i].z * vb[2].x + pa[i].w * vb[3].x;
                o[i][1] += pa[i].x * vb[0].y + pa[i].y * vb[1].y + pa[i].z * vb[2].y + pa[i].w * vb[3].y;
                o[i][2] += pa[i].x * vb[0].z + pa[i].y * vb[1].z + pa[i].z * vb[2].z + pa[i].w * vb[3].z;
                o[i][3] += pa[i].x * vb[0].w + pa[i].y * vb[1].w + pa[i].z * vb[2].w + pa[i].w * vb[3].w;
            }
        }
        __syncthreads();
    }

    const int b = bh >> 4, h = bh & 15;
    float* AO = g_AO + (size_t)(b * S_ + qt) * H_ + h * D_;
#pragma unroll
    for (int i = 0; i < 4; i++) {
        const float invl = 1.0f / l_[i];
        float4 v;
        v.x = o[i][0] * invl;
        v.y = o[i][1] * invl;
        v.z = o[i][2] * invl;
        v.w = o[i][3] * invl;
        *(float4*)(AO + (size_t)(r0 + i) * H_ + c0) = v;
    }
}

// ---------------------------------------------------------------------------
// kernel_launch: converts + 4 tensor GEMMs + attention. Graph-capturable.
// ---------------------------------------------------------------------------
extern "C" void kernel_launch(void* const* d_in, const int* in_sizes, int n_in,
                              void* d_out, int out_size)
{
    const float* q  = (const float*)d_in[0];
    const float* k  = (const float*)d_in[1];
    const float* v  = (const float*)d_in[2];
    const float* wq = (const float*)d_in[3];
    const float* bq = (const float*)d_in[4];
    const float* wk = (const float*)d_in[5];
    const float* bk = (const float*)d_in[6];
    const float* wv = (const float*)d_in[7];
    const float* bv = (const float*)d_in[8];
    const float* wo = (const float*)d_in[9];
    const float* bo = (const float*)d_in[10];
    float* out = (float*)d_out;

    float *Qp, *Kp, *Vp, *AOp;
    cudaGetSymbolAddress((void**)&Qp,  g_Q);
    cudaGetSymbolAddress((void**)&Kp,  g_K);
    cudaGetSymbolAddress((void**)&Vp,  g_V);
    cudaGetSymbolAddress((void**)&AOp, g_AO);

    __nv_bfloat16 *qhi, *qlo, *khi, *klo, *vhi, *vlo;
    __nv_bfloat16 *wqhi, *wqlo, *wkhi, *wklo, *wvhi, *wvlo, *wohi, *wolo;
    cudaGetSymbolAddress((void**)&qhi,  g_qhi);  cudaGetSymbolAddress((void**)&qlo,  g_qlo);
    cudaGetSymbolAddress((void**)&khi,  g_khi);  cudaGetSymbolAddress((void**)&klo,  g_klo);
    cudaGetSymbolAddress((void**)&vhi,  g_vhi);  cudaGetSymbolAddress((void**)&vlo,  g_vlo);
    cudaGetSymbolAddress((void**)&wqhi, g_wqhi); cudaGetSymbolAddress((void**)&wqlo, g_wqlo);
    cudaGetSymbolAddress((void**)&wkhi, g_wkhi); cudaGetSymbolAddress((void**)&wklo, g_wklo);
    cudaGetSymbolAddress((void**)&wvhi, g_wvhi); cudaGetSymbolAddress((void**)&wvlo, g_wvlo);
    cudaGetSymbolAddress((void**)&wohi, g_wohi); cudaGetSymbolAddress((void**)&wolo, g_wolo);
    // AO split reuses the Q split buffers (Q's split is consumed by GEMM 1
    // strictly before attention writes g_AO, so no overlap of live ranges).
    __nv_bfloat16 *aohi = qhi, *aolo = qlo;

    const int attn_smem = 4 * 64 * AP * (int)sizeof(float);
    cudaFuncSetAttribute(attn_kernel, cudaFuncAttributeMaxDynamicSharedMemorySize, attn_smem);

    const int actBlocks = (NACT / 4 + 255) / 256;
    const int wgtBlocks = (NWGT / 4 + 255) / 256;

    convert_kernel<<<actBlocks, 256>>>(q,  qhi,  qlo,  NACT / 4);
    convert_kernel<<<actBlocks, 256>>>(k,  khi,  klo,  NACT / 4);
    convert_kernel<<<actBlocks, 256>>>(v,  vhi,  vlo,  NACT / 4);
    convert_kernel<<<wgtBlocks, 256>>>(wq, wqhi, wqlo, NWGT / 4);
    convert_kernel<<<wgtBlocks, 256>>>(wk, wkhi, wklo, NWGT / 4);
    convert_kernel<<<wgtBlocks, 256>>>(wv, wvhi, wvlo, NWGT / 4);
    convert_kernel<<<wgtBlocks, 256>>>(wo, wohi, wolo, NWGT / 4);

    dim3 gg(16, 64), bb(256);
    mma_gemm_kernel<<<gg, bb>>>(qhi, qlo, wqhi, wqlo, bq, Qp, 1);
    mma_gemm_kernel<<<gg, bb>>>(khi, klo, wkhi, wklo, bk, Kp, 1);
    mma_gemm_kernel<<<gg, bb>>>(vhi, vlo, wvhi, wvlo, bv, Vp, 1);

    attn_kernel<<<dim3(32, 64), 256, attn_smem>>>();

    convert_kernel<<<actBlocks, 256>>>(AOp, aohi, aolo, NACT / 4);
    mma_gemm_kernel<<<gg, bb>>>(aohi, aolo, wohi, wolo, bo, out, 0);
}

// round 11
// speedup vs baseline: 2.9984x; 1.8432x over previous
#include <cuda_runtime.h>
#include <cuda_bf16.h>
#include <math.h>

// Problem constants
#define B_   4
#define S_   2048
#define H_   1024
#define NH_  16
#define D_   64
#define NACT (B_ * S_ * H_)      // 8,388,608 activation elements
#define NWGT (H_ * H_)           // 1,048,576 weight elements

typedef unsigned long long u64;
typedef unsigned int u32;

// ---------------------------------------------------------------------------
// Scratch (__device__ globals; allocation-free rule)
// Input splits (g_qi*) are dead after their projection GEMM; AO reuses qi.
// ---------------------------------------------------------------------------
__device__ __nv_bfloat16 g_qihi[NACT], g_qilo[NACT];   // input q split / later AO split
__device__ __nv_bfloat16 g_kihi[NACT], g_kilo[NACT];
__device__ __nv_bfloat16 g_vihi[NACT], g_vilo[NACT];
__device__ __nv_bfloat16 g_qphi[NACT], g_qplo[NACT];   // projected, [b,h,s,d], pre-scaled 0.125
__device__ __nv_bfloat16 g_kphi[NACT], g_kplo[NACT];
__device__ __nv_bfloat16 g_vphi[NACT], g_vplo[NACT];
__device__ __nv_bfloat16 g_wqhi[NWGT], g_wqlo[NWGT];
__device__ __nv_bfloat16 g_wkhi[NWGT], g_wklo[NWGT];
__device__ __nv_bfloat16 g_wvhi[NWGT], g_wvlo[NWGT];
__device__ __nv_bfloat16 g_wohi[NWGT], g_wolo[NWGT];

__device__ __forceinline__ u32 smem_u32(const void* p) {
    return (u32)__cvta_generic_to_shared(p);
}
__device__ __forceinline__ void ldsm_x4(u32& r0, u32& r1, u32& r2, u32& r3, u32 addr) {
    asm volatile("ldmatrix.sync.aligned.m8n8.x4.shared.b16 {%0,%1,%2,%3}, [%4];"
                 : "=r"(r0), "=r"(r1), "=r"(r2), "=r"(r3) : "r"(addr));
}
__device__ __forceinline__ void ldsm_x4_t(u32& r0, u32& r1, u32& r2, u32& r3, u32 addr) {
    asm volatile("ldmatrix.sync.aligned.m8n8.x4.trans.shared.b16 {%0,%1,%2,%3}, [%4];"
                 : "=r"(r0), "=r"(r1), "=r"(r2), "=r"(r3) : "r"(addr));
}
__device__ __forceinline__ void mma16816(float* d,
                                         u32 a0, u32 a1, u32 a2, u32 a3,
                                         u32 b0, u32 b1) {
    asm volatile(
        "mma.sync.aligned.m16n8k16.row.col.f32.bf16.bf16.f32 "
        "{%0,%1,%2,%3}, {%4,%5,%6,%7}, {%8,%9}, {%0,%1,%2,%3};"
        : "+f"(d[0]), "+f"(d[1]), "+f"(d[2]), "+f"(d[3])
        : "r"(a0), "r"(a1), "r"(a2), "r"(a3), "r"(b0), "r"(b1));
}
// split (x,y) into bf16x2 hi + bf16x2 lo (packed u32 each)
__device__ __forceinline__ void bsplit2(float x, float y, u32& h, u32& l) {
    __nv_bfloat162 hh = __floats2bfloat162_rn(x, y);
    float hx = __bfloat162float(__low2bfloat16(hh));
    float hy = __bfloat162float(__high2bfloat16(hh));
    __nv_bfloat162 ll = __floats2bfloat162_rn(x - hx, y - hy);
    h = *(u32*)&hh; l = *(u32*)&ll;
}

// ---------------------------------------------------------------------------
// fp32 -> bf16 (hi, lo) split (inputs + weights).
// ---------------------------------------------------------------------------
__global__ __launch_bounds__(256)
void convert_kernel(const float* __restrict__ x,
                    __nv_bfloat16* __restrict__ hi,
                    __nv_bfloat16* __restrict__ lo, int n4)
{
    int i = blockIdx.x * blockDim.x + threadIdx.x;
    if (i >= n4) return;
    float4 v = *(const float4*)(x + 4 * (size_t)i);
    u32 h0, l0, h1, l1;
    bsplit2(v.x, v.y, h0, l0);
    bsplit2(v.z, v.w, h1, l1);
    u32* hp = (u32*)(hi + 4 * (size_t)i);
    u32* lp = (u32*)(lo + 4 * (size_t)i);
    hp[0] = h0; hp[1] = h1;
    lp[0] = l0; lp[1] = l1;
}

// ---------------------------------------------------------------------------
// Tensor-core GEMM via bf16x3 mma.sync (validated in R8).
// layout 0: C fp32 row-major [M,1024]
// layout 1: C -> bf16 hi/lo pair buffers at [b,h,s,d], y=(acc+bias)*scale
// ---------------------------------------------------------------------------
#define APIT 40
#define BPIT 72

__global__ __launch_bounds__(256)
void mma_gemm_kernel(const __nv_bfloat16* __restrict__ Ahi_g,
                     const __nv_bfloat16* __restrict__ Alo_g,
                     const __nv_bfloat16* __restrict__ Whi_g,
                     const __nv_bfloat16* __restrict__ Wlo_g,
                     const float* __restrict__ bias,
                     float* __restrict__ Cf,
                     __nv_bfloat16* __restrict__ Chi,
                     __nv_bfloat16* __restrict__ Clo,
                     int layout, float scale)
{
    __shared__ __nv_bfloat16 sAhi[128 * APIT], sAlo[128 * APIT];
    __shared__ __nv_bfloat16 sBhi[32 * BPIT],  sBlo[32 * BPIT];

    const int tid = threadIdx.x;
    const int lane = tid & 31;
    const int wid = tid >> 5;
    const int wm = wid & 3;
    const int wn = wid >> 2;
    const int bm = blockIdx.y * 128;
    const int bn = blockIdx.x * 64;

    const int a_row = tid >> 1;
    const int a_chk = (tid & 1) << 4;
    const int b_row = tid >> 3;
    const int b_chk = (tid & 7) << 3;

    const int a_r = (lane & 15);
    const int a_k = (lane >> 4) << 3;
    const u32 sAhi_b = smem_u32(sAhi), sAlo_b = smem_u32(sAlo);
    const u32 sBhi_b = smem_u32(sBhi), sBlo_b = smem_u32(sBlo);
    u32 aAddr[2];
#pragma unroll
    for (int mi = 0; mi < 2; mi++)
        aAddr[mi] = ((wm * 32 + mi * 16 + a_r) * APIT + a_k) * 2;
    const int b_k = (lane & 15);
    u32 bAddr[2];
#pragma unroll
    for (int nt = 0; nt < 2; nt++)
        bAddr[nt] = (b_k * BPIT + wn * 32 + nt * 16 + ((lane >> 4) << 3)) * 2;

    float acc[2][4][4];
#pragma unroll
    for (int mi = 0; mi < 2; mi++)
#pragma unroll
        for (int ni = 0; ni < 4; ni++)
#pragma unroll
            for (int c = 0; c < 4; c++) acc[mi][ni][c] = 0.f;

    for (int k0 = 0; k0 < H_; k0 += 32) {
        {
            const size_t gofs = (size_t)(bm + a_row) * H_ + k0 + a_chk;
            const int sofs = a_row * APIT + a_chk;
            *(uint4*)&sAhi[sofs]     = *(const uint4*)(Ahi_g + gofs);
            *(uint4*)&sAhi[sofs + 8] = *(const uint4*)(Ahi_g + gofs + 8);
            *(uint4*)&sAlo[sofs]     = *(const uint4*)(Alo_g + gofs);
            *(uint4*)&sAlo[sofs + 8] = *(const uint4*)(Alo_g + gofs + 8);
        }
        {
            const size_t gofs = (size_t)(k0 + b_row) * H_ + bn + b_chk;
            const int sofs = b_row * BPIT + b_chk;
            *(uint4*)&sBhi[sofs] = *(const uint4*)(Whi_g + gofs);
            *(uint4*)&sBlo[sofs] = *(const uint4*)(Wlo_g + gofs);
        }
        __syncthreads();

#pragma unroll
        for (int s = 0; s < 2; s++) {
            u32 ah[2][4], al[2][4];
#pragma unroll
            for (int mi = 0; mi < 2; mi++) {
                ldsm_x4(ah[mi][0], ah[mi][1], ah[mi][2], ah[mi][3],
                        sAhi_b + aAddr[mi] + s * 32);
                ldsm_x4(al[mi][0], al[mi][1], al[mi][2], al[mi][3],
                        sAlo_b + aAddr[mi] + s * 32);
            }
            u32 bh[4][2], bl[4][2];
#pragma unroll
            for (int nt = 0; nt < 2; nt++) {
                u32 r0, r1, r2, r3;
                ldsm_x4_t(r0, r1, r2, r3, sBhi_b + bAddr[nt] + s * 16 * BPIT * 2);
                bh[nt * 2 + 0][0] = r0; bh[nt * 2 + 0][1] = r1;
                bh[nt * 2 + 1][0] = r2; bh[nt * 2 + 1][1] = r3;
                ldsm_x4_t(r0, r1, r2, r3, sBlo_b + bAddr[nt] + s * 16 * BPIT * 2);
                bl[nt * 2 + 0][0] = r0; bl[nt * 2 + 0][1] = r1;
                bl[nt * 2 + 1][0] = r2; bl[nt * 2 + 1][1] = r3;
            }
#pragma unroll
            for (int mi = 0; mi < 2; mi++)
#pragma unroll
                for (int ni = 0; ni < 4; ni++) {
                    float* d = acc[mi][ni];
                    mma16816(d, ah[mi][0], ah[mi][1], ah[mi][2], ah[mi][3], bh[ni][0], bh[ni][1]);
                    mma16816(d, ah[mi][0], ah[mi][1], ah[mi][2], ah[mi][3], bl[ni][0], bl[ni][1]);
                    mma16816(d, al[mi][0], al[mi][1], al[mi][2], al[mi][3], bh[ni][0], bh[ni][1]);
                }
        }
        __syncthreads();
    }

    const int gm0 = bm + wm * 32 + (lane >> 2);
    const int gn_base = bn + wn * 32 + 2 * (lane & 3);
#pragma unroll
    for (int ni = 0; ni < 4; ni++) {
        const int n = gn_base + ni * 8;
        const float2 bv = *(const float2*)(bias + n);
#pragma unroll
        for (int mi = 0; mi < 2; mi++) {
#pragma unroll
            for (int half = 0; half < 2; half++) {
                const int m = gm0 + mi * 16 + half * 8;
                float yx = (acc[mi][ni][2 * half + 0] + bv.x) * scale;
                float yy = (acc[mi][ni][2 * half + 1] + bv.y) * scale;
                if (layout == 0) {
                    *(float2*)(Cf + (size_t)m * H_ + n) = make_float2(yx, yy);
                } else {
                    const int b = m >> 11;
                    const int s = m & (S_ - 1);
                    const int h = n >> 6;
                    const int d = n & (D_ - 1);
                    const size_t ofs = ((size_t)(b * NH_ + h) * S_ + s) * D_ + d;
                    u32 hp, lp;
                    bsplit2(yx, yy, hp, lp);
                    *(u32*)(Chi + ofs) = hp;
                    *(u32*)(Clo + ofs) = lp;
                }
            }
        }
    }
}

// ---------------------------------------------------------------------------
// Tensor-core flash attention, bf16x3 both GEMMs.
// Block: 128 q rows x one (b,h). 8 warps, each warp = one m16 q tile vs all
// 64 keys per iteration. K as B-frag via non-trans ldsm (K is [key][d]);
// V as B-frag via trans ldsm (validated W pattern); P C-frag -> A-frag in regs.
// ---------------------------------------------------------------------------
#define KP 72   // smem pitch (bf16) for 64-wide tiles

__global__ __launch_bounds__(256)
void attn_mma_kernel(const __nv_bfloat16* __restrict__ qph, const __nv_bfloat16* __restrict__ qpl,
                     const __nv_bfloat16* __restrict__ kph, const __nv_bfloat16* __restrict__ kpl,
                     const __nv_bfloat16* __restrict__ vph, const __nv_bfloat16* __restrict__ vpl,
                     __nv_bfloat16* __restrict__ aoh, __nv_bfloat16* __restrict__ aol)
{
    __shared__ __nv_bfloat16 sm[4 * 64 * KP];   // K_hi | K_lo | V_hi | V_lo (Q staged here first)

    const int tid = threadIdx.x;
    const int lane = tid & 31;
    const int w = tid >> 5;
    const int bh = blockIdx.y;
    const int qt = blockIdx.x * 128;
    const size_t base = (size_t)bh * S_ * D_;

    const u32 smb = smem_u32(sm);
    const u32 KLO = 64 * KP * 2, VHI = 2 * 64 * KP * 2, VLO = 3 * 64 * KP * 2;

    // ---- stage Q (hi in first half, lo in second), load A-frags, release smem
#pragma unroll
    for (int t = 0; t < 4; t++) {
        const int idx = t * 256 + tid;
        const int row = idx >> 3, c8 = (idx & 7) << 3;
        const size_t g = base + (size_t)(qt + row) * D_ + c8;
        *(uint4*)&sm[row * KP + c8]            = *(const uint4*)(qph + g);
        *(uint4*)&sm[128 * KP + row * KP + c8] = *(const uint4*)(qpl + g);
    }
    __syncthreads();

    u32 qfh[4][4], qfl[4][4];
    {
        const int r = lane & 15, ko = (lane >> 4) << 3;
#pragma unroll
        for (int s = 0; s < 4; s++) {
            const u32 addr = smb + (((w * 16 + r) * KP) + s * 16 + ko) * 2;
            ldsm_x4(qfh[s][0], qfh[s][1], qfh[s][2], qfh[s][3], addr);
            ldsm_x4(qfl[s][0], qfl[s][1], qfl[s][2], qfl[s][3], addr + 128 * KP * 2);
        }
    }

    float oacc[8][4];
#pragma unroll
    for (int j = 0; j < 8; j++)
#pragma unroll
        for (int c = 0; c < 4; c++) oacc[j][c] = 0.f;
    float m_lo = -1e30f, m_hi = -1e30f, l_lo = 0.f, l_hi = 0.f;

    // fragment address components
    const int k_row = ((lane >> 4) << 3) + (lane & 7);        // + jp*16
    const int k_col = ((lane >> 3) & 1) << 3;                 // + s*16
    const int v_row = lane & 15;                              // + t*16
    const int v_col = (lane >> 4) << 3;                       // + up*16

    for (int kv0 = 0; kv0 < S_; kv0 += 64) {
        __syncthreads();   // previous iteration's smem reads complete
#pragma unroll
        for (int t = 0; t < 2; t++) {
            const int idx = t * 256 + tid;
            const int row = idx >> 3, c8 = (idx & 7) << 3;
            const size_t g = base + (size_t)(kv0 + row) * D_ + c8;
            const int s_ = row * KP + c8;
            *(uint4*)&sm[s_]                 = *(const uint4*)(kph + g);
            *(uint4*)&sm[64 * KP + s_]       = *(const uint4*)(kpl + g);
            *(uint4*)&sm[2 * 64 * KP + s_]   = *(const uint4*)(vph + g);
            *(uint4*)&sm[3 * 64 * KP + s_]   = *(const uint4*)(vpl + g);
        }
        __syncthreads();

        // ---- S = Q K^T (bf16x3)
        float sacc[8][4];
#pragma unroll
        for (int j = 0; j < 8; j++)
#pragma unroll
            for (int c = 0; c < 4; c++) sacc[j][c] = 0.f;

#pragma unroll
        for (int s = 0; s < 4; s++) {
#pragma unroll
            for (int jp = 0; jp < 4; jp++) {
                u32 h0, h1, h2, h3, l0, l1, l2, l3;
                const u32 addr = smb + ((jp * 16 + k_row) * KP + s * 16 + k_col) * 2;
                ldsm_x4(h0, h1, h2, h3, addr);
                ldsm_x4(l0, l1, l2, l3, addr + KLO);
                mma16816(sacc[2 * jp],     qfh[s][0], qfh[s][1], qfh[s][2], qfh[s][3], h0, h1);
                mma16816(sacc[2 * jp],     qfh[s][0], qfh[s][1], qfh[s][2], qfh[s][3], l0, l1);
                mma16816(sacc[2 * jp],     qfl[s][0], qfl[s][1], qfl[s][2], qfl[s][3], h0, h1);
                mma16816(sacc[2 * jp + 1], qfh[s][0], qfh[s][1], qfh[s][2], qfh[s][3], h2, h3);
                mma16816(sacc[2 * jp + 1], qfh[s][0], qfh[s][1], qfh[s][2], qfh[s][3], l2, l3);
                mma16816(sacc[2 * jp + 1], qfl[s][0], qfl[s][1], qfl[s][2], qfl[s][3], h2, h3);
            }
        }

        // ---- online softmax (rows r = w*16 + lane>>2 and +8)
        float mt_lo = -1e30f, mt_hi = -1e30f;
#pragma unroll
        for (int j = 0; j < 8; j++) {
            mt_lo = fmaxf(mt_lo, fmaxf(sacc[j][0], sacc[j][1]));
            mt_hi = fmaxf(mt_hi, fmaxf(sacc[j][2], sacc[j][3]));
        }
        mt_lo = fmaxf(mt_lo, __shfl_xor_sync(0xffffffffu, mt_lo, 1));
        mt_lo = fmaxf(mt_lo, __shfl_xor_sync(0xffffffffu, mt_lo, 2));
        mt_hi = fmaxf(mt_hi, __shfl_xor_sync(0xffffffffu, mt_hi, 1));
        mt_hi = fmaxf(mt_hi, __shfl_xor_sync(0xffffffffu, mt_hi, 2));

        const float mn_lo = fmaxf(m_lo, mt_lo), mn_hi = fmaxf(m_hi, mt_hi);
        const float f_lo = __expf(m_lo - mn_lo), f_hi = __expf(m_hi - mn_hi);
        float rs_lo = 0.f, rs_hi = 0.f;
#pragma unroll
        for (int j = 0; j < 8; j++) {
            sacc[j][0] = __expf(sacc[j][0] - mn_lo);
            sacc[j][1] = __expf(sacc[j][1] - mn_lo);
            sacc[j][2] = __expf(sacc[j][2] - mn_hi);
            sacc[j][3] = __expf(sacc[j][3] - mn_hi);
            rs_lo += sacc[j][0] + sacc[j][1];
            rs_hi += sacc[j][2] + sacc[j][3];
        }
        rs_lo += __shfl_xor_sync(0xffffffffu, rs_lo, 1);
        rs_lo += __shfl_xor_sync(0xffffffffu, rs_lo, 2);
        rs_hi += __shfl_xor_sync(0xffffffffu, rs_hi, 1);
        rs_hi += __shfl_xor_sync(0xffffffffu, rs_hi, 2);
        l_lo = l_lo * f_lo + rs_lo;  m_lo = mn_lo;
        l_hi = l_hi * f_hi + rs_hi;  m_hi = mn_hi;
#pragma unroll
        for (int j = 0; j < 8; j++) {
            oacc[j][0] *= f_lo; oacc[j][1] *= f_lo;
            oacc[j][2] *= f_hi; oacc[j][3] *= f_hi;
        }

        // ---- O += P V (bf16x3); P C-frag -> A-frag in registers
#pragma unroll
        for (int t = 0; t < 4; t++) {
            u32 ph[4], pl[4];
            bsplit2(sacc[2 * t][0],     sacc[2 * t][1],     ph[0], pl[0]);
            bsplit2(sacc[2 * t][2],     sacc[2 * t][3],     ph[1], pl[1]);
            bsplit2(sacc[2 * t + 1][0], sacc[2 * t + 1][1], ph[2], pl[2]);
            bsplit2(sacc[2 * t + 1][2], sacc[2 * t + 1][3], ph[3], pl[3]);
#pragma unroll
            for (int up = 0; up < 4; up++) {
                u32 h0, h1, h2, h3, l0, l1, l2, l3;
                const u32 addr = smb + VHI + ((t * 16 + v_row) * KP + up * 16 + v_col) * 2;
                ldsm_x4_t(h0, h1, h2, h3, addr);
                ldsm_x4_t(l0, l1, l2, l3, addr + (VLO - VHI));
                mma16816(oacc[2 * up],     ph[0], ph[1], ph[2], ph[3], h0, h1);
                mma16816(oacc[2 * up],     pl[0], pl[1], pl[2], pl[3], h0, h1);
                mma16816(oacc[2 * up],     ph[0], ph[1], ph[2], ph[3], l0, l1);
                mma16816(oacc[2 * up + 1], ph[0], ph[1], ph[2], ph[3], h2, h3);
                mma16816(oacc[2 * up + 1], pl[0], pl[1], pl[2], pl[3], h2, h3);
                mma16816(oacc[2 * up + 1], ph[0], ph[1], ph[2], ph[3], l2, l3);
            }
        }
    }

    // ---- epilogue: normalize, split hi/lo, write AO [b, s, h*64+d]
    const float il_lo = 1.f / l_lo, il_hi = 1.f / l_hi;
    const int r_lo = qt + w * 16 + (lane >> 2);
    const int r_hi = r_lo + 8;
    const int b = bh >> 4, h = bh & 15;
    const int colb = h * 64 + 2 * (lane & 3);
#pragma unroll
    for (int j = 0; j < 8; j++) {
        const int col = colb + j * 8;
        u32 hp, lp;
        bsplit2(oacc[j][0] * il_lo, oacc[j][1] * il_lo, hp, lp);
        size_t ofs = (size_t)(b * S_ + r_lo) * H_ + col;
        *(u32*)(aoh + ofs) = hp;
        *(u32*)(aol + ofs) = lp;
        bsplit2(oacc[j][2] * il_hi, oacc[j][3] * il_hi, hp, lp);
        ofs = (size_t)(b * S_ + r_hi) * H_ + col;
        *(u32*)(aoh + ofs) = hp;
        *(u32*)(aol + ofs) = lp;
    }
}

// ---------------------------------------------------------------------------
// kernel_launch: 7 converts + 3 proj GEMMs + attn + out GEMM. Graph-capturable.
// ---------------------------------------------------------------------------
extern "C" void kernel_launch(void* const* d_in, const int* in_sizes, int n_in,
                              void* d_out, int out_size)
{
    const float* q  = (const float*)d_in[0];
    const float* k  = (const float*)d_in[1];
    const float* v  = (const float*)d_in[2];
    const float* wq = (const float*)d_in[3];
    const float* bq = (const float*)d_in[4];
    const float* wk = (const float*)d_in[5];
    const float* bk = (const float*)d_in[6];
    const float* wv = (const float*)d_in[7];
    const float* bv = (const float*)d_in[8];
    const float* wo = (const float*)d_in[9];
    const float* bo = (const float*)d_in[10];
    float* out = (float*)d_out;

    __nv_bfloat16 *qihi, *qilo, *kihi, *kilo, *vihi, *vilo;
    __nv_bfloat16 *qphi, *qplo, *kphi, *kplo, *vphi, *vplo;
    __nv_bfloat16 *wqhi, *wqlo, *wkhi, *wklo, *wvhi, *wvlo, *wohi, *wolo;
    cudaGetSymbolAddress((void**)&qihi, g_qihi); cudaGetSymbolAddress((void**)&qilo, g_qilo);
    cudaGetSymbolAddress((void**)&kihi, g_kihi); cudaGetSymbolAddress((void**)&kilo, g_kilo);
    cudaGetSymbolAddress((void**)&vihi, g_vihi); cudaGetSymbolAddress((void**)&vilo, g_vilo);
    cudaGetSymbolAddress((void**)&qphi, g_qphi); cudaGetSymbolAddress((void**)&qplo, g_qplo);
    cudaGetSymbolAddress((void**)&kphi, g_kphi); cudaGetSymbolAddress((void**)&kplo, g_kplo);
    cudaGetSymbolAddress((void**)&vphi, g_vphi); cudaGetSymbolAddress((void**)&vplo, g_vplo);
    cudaGetSymbolAddress((void**)&wqhi, g_wqhi); cudaGetSymbolAddress((void**)&wqlo, g_wqlo);
    cudaGetSymbolAddress((void**)&wkhi, g_wkhi); cudaGetSymbolAddress((void**)&wklo, g_wklo);
    cudaGetSymbolAddress((void**)&wvhi, g_wvhi); cudaGetSymbolAddress((void**)&wvlo, g_wvlo);
    cudaGetSymbolAddress((void**)&wohi, g_wohi); cudaGetSymbolAddress((void**)&wolo, g_wolo);
    // AO split reuses input-q split buffers (dead after the Q projection GEMM)
    __nv_bfloat16 *aohi = qihi, *aolo = qilo;

    const int actBlocks = (NACT / 4 + 255) / 256;
    const int wgtBlocks = (NWGT / 4 + 255) / 256;

    convert_kernel<<<actBlocks, 256>>>(q,  qihi, qilo, NACT / 4);
    convert_kernel<<<actBlocks, 256>>>(k,  kihi, kilo, NACT / 4);
    convert_kernel<<<actBlocks, 256>>>(v,  vihi, vilo, NACT / 4);
    convert_kernel<<<wgtBlocks, 256>>>(wq, wqhi, wqlo, NWGT / 4);
    convert_kernel<<<wgtBlocks, 256>>>(wk, wkhi, wklo, NWGT / 4);
    convert_kernel<<<wgtBlocks, 256>>>(wv, wvhi, wvlo, NWGT / 4);
    convert_kernel<<<wgtBlocks, 256>>>(wo, wohi, wolo, NWGT / 4);

    dim3 gg(16, 64), bb(256);
    // Q projection pre-scaled by 1/sqrt(D)=0.125
    mma_gemm_kernel<<<gg, bb>>>(qihi, qilo, wqhi, wqlo, bq, nullptr, qphi, qplo, 1, 0.125f);
    mma_gemm_kernel<<<gg, bb>>>(kihi, kilo, wkhi, wklo, bk, nullptr, kphi, kplo, 1, 1.0f);
    mma_gemm_kernel<<<gg, bb>>>(vihi, vilo, wvhi, wvlo, bv, nullptr, vphi, vplo, 1, 1.0f);

    attn_mma_kernel<<<dim3(16, 64), 256>>>(qphi, qplo, kphi, kplo, vphi, vplo, aohi, aolo);

    mma_gemm_kernel<<<gg, bb>>>(aohi, aolo, wohi, wolo, bo, out, nullptr, nullptr, 0, 1.0f);
}

// round 12
// speedup vs baseline: 3.5193x; 1.1737x over previous
#include <cuda_runtime.h>
#include <cuda_bf16.h>
#include <math.h>

// Problem constants
#define B_   4
#define S_   2048
#define H_   1024
#define NH_  16
#define D_   64
#define NACT (B_ * S_ * H_)
#define NWGT (H_ * H_)

typedef unsigned long long u64;
typedef unsigned int u32;

// ---------------------------------------------------------------------------
// Scratch (__device__ globals; allocation-free rule)
// ---------------------------------------------------------------------------
__device__ __nv_bfloat16 g_qihi[NACT], g_qilo[NACT];   // input q split / later AO split
__device__ __nv_bfloat16 g_kihi[NACT], g_kilo[NACT];
__device__ __nv_bfloat16 g_vihi[NACT], g_vilo[NACT];
__device__ __nv_bfloat16 g_qphi[NACT], g_qplo[NACT];   // projected [b,h,s,d], pre-scaled 0.125
__device__ __nv_bfloat16 g_kphi[NACT], g_kplo[NACT];
__device__ __nv_bfloat16 g_vphi[NACT], g_vplo[NACT];
__device__ __nv_bfloat16 g_wqhi[NWGT], g_wqlo[NWGT];
__device__ __nv_bfloat16 g_wkhi[NWGT], g_wklo[NWGT];
__device__ __nv_bfloat16 g_wvhi[NWGT], g_wvlo[NWGT];
__device__ __nv_bfloat16 g_wohi[NWGT], g_wolo[NWGT];

__device__ __forceinline__ u32 smem_u32(const void* p) {
    return (u32)__cvta_generic_to_shared(p);
}
__device__ __forceinline__ void cp16(u32 dst, const void* src) {
    asm volatile("cp.async.cg.shared.global [%0], [%1], 16;" :: "r"(dst), "l"(src));
}
#define CP_COMMIT() asm volatile("cp.async.commit_group;")
#define CP_WAIT1()  asm volatile("cp.async.wait_group 1;")
__device__ __forceinline__ void ldsm_x4(u32& r0, u32& r1, u32& r2, u32& r3, u32 addr) {
    asm volatile("ldmatrix.sync.aligned.m8n8.x4.shared.b16 {%0,%1,%2,%3}, [%4];"
                 : "=r"(r0), "=r"(r1), "=r"(r2), "=r"(r3) : "r"(addr));
}
__device__ __forceinline__ void ldsm_x4_t(u32& r0, u32& r1, u32& r2, u32& r3, u32 addr) {
    asm volatile("ldmatrix.sync.aligned.m8n8.x4.trans.shared.b16 {%0,%1,%2,%3}, [%4];"
                 : "=r"(r0), "=r"(r1), "=r"(r2), "=r"(r3) : "r"(addr));
}
__device__ __forceinline__ void mma16816(float* d,
                                         u32 a0, u32 a1, u32 a2, u32 a3,
                                         u32 b0, u32 b1) {
    asm volatile(
        "mma.sync.aligned.m16n8k16.row.col.f32.bf16.bf16.f32 "
        "{%0,%1,%2,%3}, {%4,%5,%6,%7}, {%8,%9}, {%0,%1,%2,%3};"
        : "+f"(d[0]), "+f"(d[1]), "+f"(d[2]), "+f"(d[3])
        : "r"(a0), "r"(a1), "r"(a2), "r"(a3), "r"(b0), "r"(b1));
}
__device__ __forceinline__ void bsplit2(float x, float y, u32& h, u32& l) {
    __nv_bfloat162 hh = __floats2bfloat162_rn(x, y);
    float hx = __bfloat162float(__low2bfloat16(hh));
    float hy = __bfloat162float(__high2bfloat16(hh));
    __nv_bfloat162 ll = __floats2bfloat162_rn(x - hx, y - hy);
    h = *(u32*)&hh; l = *(u32*)&ll;
}

// ---------------------------------------------------------------------------
// fp32 -> bf16 (hi, lo) split
// ---------------------------------------------------------------------------
__global__ __launch_bounds__(256)
void convert_kernel(const float* __restrict__ x,
                    __nv_bfloat16* __restrict__ hi,
                    __nv_bfloat16* __restrict__ lo, int n4)
{
    int i = blockIdx.x * blockDim.x + threadIdx.x;
    if (i >= n4) return;
    float4 v = *(const float4*)(x + 4 * (size_t)i);
    u32 h0, l0, h1, l1;
    bsplit2(v.x, v.y, h0, l0);
    bsplit2(v.z, v.w, h1, l1);
    u32* hp = (u32*)(hi + 4 * (size_t)i);
    u32* lp = (u32*)(lo + 4 * (size_t)i);
    hp[0] = h0; hp[1] = h1;
    lp[0] = l0; lp[1] = l1;
}

// ---------------------------------------------------------------------------
// Tensor-core GEMM, bf16x3 mma.sync, 2-stage cp.async double-buffered.
// Stage layout (bytes): Ahi[0,10240) Alo[10240,20480) Bhi[20480,25088) Blo[25088,29696)
// ---------------------------------------------------------------------------
#define APIT 40
#define BPIT 72
#define G_AHI 0
#define G_ALO 10240
#define G_BHI 20480
#define G_BLO 25088
#define G_STG 29696            // bytes per stage

__global__ __launch_bounds__(256)
void mma_gemm_kernel(const __nv_bfloat16* __restrict__ Ahi_g,
                     const __nv_bfloat16* __restrict__ Alo_g,
                     const __nv_bfloat16* __restrict__ Whi_g,
                     const __nv_bfloat16* __restrict__ Wlo_g,
                     const float* __restrict__ bias,
                     float* __restrict__ Cf,
                     __nv_bfloat16* __restrict__ Chi,
                     __nv_bfloat16* __restrict__ Clo,
                     int layout, float scale)
{
    extern __shared__ __nv_bfloat16 dsm[];
    const u32 smb = smem_u32(dsm);

    const int tid = threadIdx.x;
    const int lane = tid & 31;
    const int wid = tid >> 5;
    const int wm = wid & 3;
    const int wn = wid >> 2;
    const int bm = blockIdx.y * 128;
    const int bn = blockIdx.x * 64;

    const int a_row = tid >> 1;
    const int a_chk = (tid & 1) << 4;
    const int b_row = tid >> 3;
    const int b_chk = (tid & 7) << 3;

    const int a_r = (lane & 15);
    const int a_k = (lane >> 4) << 3;
    u32 aAddr[2];
#pragma unroll
    for (int mi = 0; mi < 2; mi++)
        aAddr[mi] = ((wm * 32 + mi * 16 + a_r) * APIT + a_k) * 2;
    const int b_k = (lane & 15);
    u32 bAddr[2];
#pragma unroll
    for (int nt = 0; nt < 2; nt++)
        bAddr[nt] = (b_k * BPIT + wn * 32 + nt * 16 + ((lane >> 4) << 3)) * 2;

    // cp.async loader for k-tile at k0 into stage stg
    auto load_tiles = [&](int k0, int stg) {
        const u32 sb = smb + stg * G_STG;
        const size_t ga = (size_t)(bm + a_row) * H_ + k0 + a_chk;
        const u32 sa = (a_row * APIT + a_chk) * 2;
        cp16(sb + G_AHI + sa,      Ahi_g + ga);
        cp16(sb + G_AHI + sa + 16, Ahi_g + ga + 8);
        cp16(sb + G_ALO + sa,      Alo_g + ga);
        cp16(sb + G_ALO + sa + 16, Alo_g + ga + 8);
        const size_t gb = (size_t)(k0 + b_row) * H_ + bn + b_chk;
        const u32 sbo = (b_row * BPIT + b_chk) * 2;
        cp16(sb + G_BHI + sbo, Whi_g + gb);
        cp16(sb + G_BLO + sbo, Wlo_g + gb);
    };

    float acc[2][4][4];
#pragma unroll
    for (int mi = 0; mi < 2; mi++)
#pragma unroll
        for (int ni = 0; ni < 4; ni++)
#pragma unroll
            for (int c = 0; c < 4; c++) acc[mi][ni][c] = 0.f;

    load_tiles(0, 0);
    CP_COMMIT();

    for (int it = 0; it < 32; it++) {
        const int cur = it & 1;
        if (it < 31) load_tiles((it + 1) * 32, 1 - cur);
        CP_COMMIT();
        CP_WAIT1();
        __syncthreads();

        const u32 sb = smb + cur * G_STG;
#pragma unroll
        for (int s = 0; s < 2; s++) {
            u32 ah[2][4], al[2][4];
#pragma unroll
            for (int mi = 0; mi < 2; mi++) {
                ldsm_x4(ah[mi][0], ah[mi][1], ah[mi][2], ah[mi][3],
                        sb + G_AHI + aAddr[mi] + s * 32);
                ldsm_x4(al[mi][0], al[mi][1], al[mi][2], al[mi][3],
                        sb + G_ALO + aAddr[mi] + s * 32);
            }
            u32 bh[4][2], bl[4][2];
#pragma unroll
            for (int nt = 0; nt < 2; nt++) {
                u32 r0, r1, r2, r3;
                ldsm_x4_t(r0, r1, r2, r3, sb + G_BHI + bAddr[nt] + s * 16 * BPIT * 2);
                bh[nt * 2 + 0][0] = r0; bh[nt * 2 + 0][1] = r1;
                bh[nt * 2 + 1][0] = r2; bh[nt * 2 + 1][1] = r3;
                ldsm_x4_t(r0, r1, r2, r3, sb + G_BLO + bAddr[nt] + s * 16 * BPIT * 2);
                bl[nt * 2 + 0][0] = r0; bl[nt * 2 + 0][1] = r1;
                bl[nt * 2 + 1][0] = r2; bl[nt * 2 + 1][1] = r3;
            }
#pragma unroll
            for (int mi = 0; mi < 2; mi++)
#pragma unroll
                for (int ni = 0; ni < 4; ni++) {
                    float* d = acc[mi][ni];
                    mma16816(d, ah[mi][0], ah[mi][1], ah[mi][2], ah[mi][3], bh[ni][0], bh[ni][1]);
                    mma16816(d, ah[mi][0], ah[mi][1], ah[mi][2], ah[mi][3], bl[ni][0], bl[ni][1]);
                    mma16816(d, al[mi][0], al[mi][1], al[mi][2], al[mi][3], bh[ni][0], bh[ni][1]);
                }
        }
        __syncthreads();
    }

    const int gm0 = bm + wm * 32 + (lane >> 2);
    const int gn_base = bn + wn * 32 + 2 * (lane & 3);
#pragma unroll
    for (int ni = 0; ni < 4; ni++) {
        const int n = gn_base + ni * 8;
        const float2 bv = *(const float2*)(bias + n);
#pragma unroll
        for (int mi = 0; mi < 2; mi++) {
#pragma unroll
            for (int half = 0; half < 2; half++) {
                const int m = gm0 + mi * 16 + half * 8;
                float yx = (acc[mi][ni][2 * half + 0] + bv.x) * scale;
                float yy = (acc[mi][ni][2 * half + 1] + bv.y) * scale;
                if (layout == 0) {
                    *(float2*)(Cf + (size_t)m * H_ + n) = make_float2(yx, yy);
                } else {
                    const int b = m >> 11;
                    const int s = m & (S_ - 1);
                    const int h = n >> 6;
                    const int d = n & (D_ - 1);
                    const size_t ofs = ((size_t)(b * NH_ + h) * S_ + s) * D_ + d;
                    u32 hp, lp;
                    bsplit2(yx, yy, hp, lp);
                    *(u32*)(Chi + ofs) = hp;
                    *(u32*)(Clo + ofs) = lp;
                }
            }
        }
    }
}

// ---------------------------------------------------------------------------
// Tensor-core flash attention, bf16x3, 2-stage cp.async K/V pipeline.
// Stage (bytes): Khi[0) Klo[+36864/4...] -> per-matrix block = 64*KP*2 bytes.
// Q staged in stage-0 region before the pipeline starts.
// ---------------------------------------------------------------------------
#define KP 72
#define A_MAT (64 * KP * 2)      // bytes per matrix block
#define A_STG (4 * A_MAT)        // 36,864 B per stage

__global__ __launch_bounds__(256)
void attn_mma_kernel(const __nv_bfloat16* __restrict__ qph, const __nv_bfloat16* __restrict__ qpl,
                     const __nv_bfloat16* __restrict__ kph, const __nv_bfloat16* __restrict__ kpl,
                     const __nv_bfloat16* __restrict__ vph, const __nv_bfloat16* __restrict__ vpl,
                     __nv_bfloat16* __restrict__ aoh, __nv_bfloat16* __restrict__ aol)
{
    extern __shared__ __nv_bfloat16 dsm[];
    const u32 smb = smem_u32(dsm);

    const int tid = threadIdx.x;
    const int lane = tid & 31;
    const int w = tid >> 5;
    const int bh = blockIdx.y;
    const int qt = blockIdx.x * 128;
    const size_t base = (size_t)bh * S_ * D_;

    // ---- stage Q in stage-0 region, load A-frags
#pragma unroll
    for (int t = 0; t < 4; t++) {
        const int idx = t * 256 + tid;
        const int row = idx >> 3, c8 = (idx & 7) << 3;
        const size_t g = base + (size_t)(qt + row) * D_ + c8;
        *(uint4*)&dsm[row * KP + c8]            = *(const uint4*)(qph + g);
        *(uint4*)&dsm[128 * KP + row * KP + c8] = *(const uint4*)(qpl + g);
    }
    __syncthreads();

    u32 qfh[4][4], qfl[4][4];
    {
        const int r = lane & 15, ko = (lane >> 4) << 3;
#pragma unroll
        for (int s = 0; s < 4; s++) {
            const u32 addr = smb + (((w * 16 + r) * KP) + s * 16 + ko) * 2;
            ldsm_x4(qfh[s][0], qfh[s][1], qfh[s][2], qfh[s][3], addr);
            ldsm_x4(qfl[s][0], qfl[s][1], qfl[s][2], qfl[s][3], addr + 128 * KP * 2);
        }
    }
    __syncthreads();   // all warps done reading Q before stage 0 is overwritten

    const __nv_bfloat16* mats[4] = {kph, kpl, vph, vpl};
    auto load_kv = [&](int kv0, int stg) {
#pragma unroll
        for (int t = 0; t < 8; t++) {
            const int mat = t >> 1;
            const int idx = t * 256 + tid;
            const int row = (idx >> 3) & 63;
            const int c8 = (idx & 7) << 3;
            const u32 dst = smb + stg * A_STG + mat * A_MAT + (row * KP + c8) * 2;
            cp16(dst, mats[mat] + base + (size_t)(kv0 + row) * D_ + c8);
        }
    };

    float oacc[8][4];
#pragma unroll
    for (int j = 0; j < 8; j++)
#pragma unroll
        for (int c = 0; c < 4; c++) oacc[j][c] = 0.f;
    float m_lo = -1e30f, m_hi = -1e30f, l_lo = 0.f, l_hi = 0.f;

    const int k_row = ((lane >> 4) << 3) + (lane & 7);
    const int k_col = ((lane >> 3) & 1) << 3;
    const int v_row = lane & 15;
    const int v_col = (lane >> 4) << 3;

    load_kv(0, 0);
    CP_COMMIT();

    for (int it = 0; it < 32; it++) {
        const int cur = it & 1;
        if (it < 31) load_kv((it + 1) * 64, 1 - cur);
        CP_COMMIT();
        CP_WAIT1();
        __syncthreads();

        const u32 sb = smb + cur * A_STG;

        // ---- S = Q K^T (bf16x3)
        float sacc[8][4];
#pragma unroll
        for (int j = 0; j < 8; j++)
#pragma unroll
            for (int c = 0; c < 4; c++) sacc[j][c] = 0.f;

#pragma unroll
        for (int s = 0; s < 4; s++) {
#pragma unroll
            for (int jp = 0; jp < 4; jp++) {
                u32 h0, h1, h2, h3, l0, l1, l2, l3;
                const u32 addr = sb + ((jp * 16 + k_row) * KP + s * 16 + k_col) * 2;
                ldsm_x4(h0, h1, h2, h3, addr);
                ldsm_x4(l0, l1, l2, l3, addr + A_MAT);
                mma16816(sacc[2 * jp],     qfh[s][0], qfh[s][1], qfh[s][2], qfh[s][3], h0, h1);
                mma16816(sacc[2 * jp],     qfh[s][0], qfh[s][1], qfh[s][2], qfh[s][3], l0, l1);
                mma16816(sacc[2 * jp],     qfl[s][0], qfl[s][1], qfl[s][2], qfl[s][3], h0, h1);
                mma16816(sacc[2 * jp + 1], qfh[s][0], qfh[s][1], qfh[s][2], qfh[s][3], h2, h3);
                mma16816(sacc[2 * jp + 1], qfh[s][0], qfh[s][1], qfh[s][2], qfh[s][3], l2, l3);
                mma16816(sacc[2 * jp + 1], qfl[s][0], qfl[s][1], qfl[s][2], qfl[s][3], h2, h3);
            }
        }

        // ---- online softmax
        float mt_lo = -1e30f, mt_hi = -1e30f;
#pragma unroll
        for (int j = 0; j < 8; j++) {
            mt_lo = fmaxf(mt_lo, fmaxf(sacc[j][0], sacc[j][1]));
            mt_hi = fmaxf(mt_hi, fmaxf(sacc[j][2], sacc[j][3]));
        }
        mt_lo = fmaxf(mt_lo, __shfl_xor_sync(0xffffffffu, mt_lo, 1));
        mt_lo = fmaxf(mt_lo, __shfl_xor_sync(0xffffffffu, mt_lo, 2));
        mt_hi = fmaxf(mt_hi, __shfl_xor_sync(0xffffffffu, mt_hi, 1));
        mt_hi = fmaxf(mt_hi, __shfl_xor_sync(0xffffffffu, mt_hi, 2));

        const float mn_lo = fmaxf(m_lo, mt_lo), mn_hi = fmaxf(m_hi, mt_hi);
        const float f_lo = __expf(m_lo - mn_lo), f_hi = __expf(m_hi - mn_hi);
        float rs_lo = 0.f, rs_hi = 0.f;
#pragma unroll
        for (int j = 0; j < 8; j++) {
            sacc[j][0] = __expf(sacc[j][0] - mn_lo);
            sacc[j][1] = __expf(sacc[j][1] - mn_lo);
            sacc[j][2] = __expf(sacc[j][2] - mn_hi);
            sacc[j][3] = __expf(sacc[j][3] - mn_hi);
            rs_lo += sacc[j][0] + sacc[j][1];
            rs_hi += sacc[j][2] + sacc[j][3];
        }
        rs_lo += __shfl_xor_sync(0xffffffffu, rs_lo, 1);
        rs_lo += __shfl_xor_sync(0xffffffffu, rs_lo, 2);
        rs_hi += __shfl_xor_sync(0xffffffffu, rs_hi, 1);
        rs_hi += __shfl_xor_sync(0xffffffffu, rs_hi, 2);
        l_lo = l_lo * f_lo + rs_lo;  m_lo = mn_lo;
        l_hi = l_hi * f_hi + rs_hi;  m_hi = mn_hi;
#pragma unroll
        for (int j = 0; j < 8; j++) {
            oacc[j][0] *= f_lo; oacc[j][1] *= f_lo;
            oacc[j][2] *= f_hi; oacc[j][3] *= f_hi;
        }

        // ---- O += P V (bf16x3)
#pragma unroll
        for (int t = 0; t < 4; t++) {
            u32 ph[4], pl[4];
            bsplit2(sacc[2 * t][0],     sacc[2 * t][1],     ph[0], pl[0]);
            bsplit2(sacc[2 * t][2],     sacc[2 * t][3],     ph[1], pl[1]);
            bsplit2(sacc[2 * t + 1][0], sacc[2 * t + 1][1], ph[2], pl[2]);
            bsplit2(sacc[2 * t + 1][2], sacc[2 * t + 1][3], ph[3], pl[3]);
#pragma unroll
            for (int up = 0; up < 4; up++) {
                u32 h0, h1, h2, h3, l0, l1, l2, l3;
                const u32 addr = sb + 2 * A_MAT + ((t * 16 + v_row) * KP + up * 16 + v_col) * 2;
                ldsm_x4_t(h0, h1, h2, h3, addr);
                ldsm_x4_t(l0, l1, l2, l3, addr + A_MAT);
                mma16816(oacc[2 * up],     ph[0], ph[1], ph[2], ph[3], h0, h1);
                mma16816(oacc[2 * up],     pl[0], pl[1], pl[2], pl[3], h0, h1);
                mma16816(oacc[2 * up],     ph[0], ph[1], ph[2], ph[3], l0, l1);
                mma16816(oacc[2 * up + 1], ph[0], ph[1], ph[2], ph[3], h2, h3);
                mma16816(oacc[2 * up + 1], pl[0], pl[1], pl[2], pl[3], h2, h3);
                mma16816(oacc[2 * up + 1], ph[0], ph[1], ph[2], ph[3], l2, l3);
            }
        }
        __syncthreads();
    }

    // ---- epilogue
    const float il_lo = 1.f / l_lo, il_hi = 1.f / l_hi;
    const int r_lo = qt + w * 16 + (lane >> 2);
    const int r_hi = r_lo + 8;
    const int b = bh >> 4, h = bh & 15;
    const int colb = h * 64 + 2 * (lane & 3);
#pragma unroll
    for (int j = 0; j < 8; j++) {
        const int col = colb + j * 8;
        u32 hp, lp;
        bsplit2(oacc[j][0] * il_lo, oacc[j][1] * il_lo, hp, lp);
        size_t ofs = (size_t)(b * S_ + r_lo) * H_ + col;
        *(u32*)(aoh + ofs) = hp;
        *(u32*)(aol + ofs) = lp;
        bsplit2(oacc[j][2] * il_hi, oacc[j][3] * il_hi, hp, lp);
        ofs = (size_t)(b * S_ + r_hi) * H_ + col;
        *(u32*)(aoh + ofs) = hp;
        *(u32*)(aol + ofs) = lp;
    }
}

// ---------------------------------------------------------------------------
// kernel_launch
// ---------------------------------------------------------------------------
extern "C" void kernel_launch(void* const* d_in, const int* in_sizes, int n_in,
                              void* d_out, int out_size)
{
    const float* q  = (const float*)d_in[0];
    const float* k  = (const float*)d_in[1];
    const float* v  = (const float*)d_in[2];
    const float* wq = (const float*)d_in[3];
    const float* bq = (const float*)d_in[4];
    const float* wk = (const float*)d_in[5];
    const float* bk = (const float*)d_in[6];
    const float* wv = (const float*)d_in[7];
    const float* bv = (const float*)d_in[8];
    const float* wo = (const float*)d_in[9];
    const float* bo = (const float*)d_in[10];
    float* out = (float*)d_out;

    __nv_bfloat16 *qihi, *qilo, *kihi, *kilo, *vihi, *vilo;
    __nv_bfloat16 *qphi, *qplo, *kphi, *kplo, *vphi, *vplo;
    __nv_bfloat16 *wqhi, *wqlo, *wkhi, *wklo, *wvhi, *wvlo, *wohi, *wolo;
    cudaGetSymbolAddress((void**)&qihi, g_qihi); cudaGetSymbolAddress((void**)&qilo, g_qilo);
    cudaGetSymbolAddress((void**)&kihi, g_kihi); cudaGetSymbolAddress((void**)&kilo, g_kilo);
    cudaGetSymbolAddress((void**)&vihi, g_vihi); cudaGetSymbolAddress((void**)&vilo, g_vilo);
    cudaGetSymbolAddress((void**)&qphi, g_qphi); cudaGetSymbolAddress((void**)&qplo, g_qplo);
    cudaGetSymbolAddress((void**)&kphi, g_kphi); cudaGetSymbolAddress((void**)&kplo, g_kplo);
    cudaGetSymbolAddress((void**)&vphi, g_vphi); cudaGetSymbolAddress((void**)&vplo, g_vplo);
    cudaGetSymbolAddress((void**)&wqhi, g_wqhi); cudaGetSymbolAddress((void**)&wqlo, g_wqlo);
    cudaGetSymbolAddress((void**)&wkhi, g_wkhi); cudaGetSymbolAddress((void**)&wklo, g_wklo);
    cudaGetSymbolAddress((void**)&wvhi, g_wvhi); cudaGetSymbolAddress((void**)&wvlo, g_wvlo);
    cudaGetSymbolAddress((void**)&wohi, g_wohi); cudaGetSymbolAddress((void**)&wolo, g_wolo);
    __nv_bfloat16 *aohi = qihi, *aolo = qilo;   // AO reuses q-input split buffers

    const int gemm_smem = 2 * G_STG;     // 59,392 B
    const int attn_smem = 2 * A_STG;     // 73,728 B
    cudaFuncSetAttribute(mma_gemm_kernel, cudaFuncAttributeMaxDynamicSharedMemorySize, gemm_smem);
    cudaFuncSetAttribute(attn_mma_kernel, cudaFuncAttributeMaxDynamicSharedMemorySize, attn_smem);

    const int actBlocks = (NACT / 4 + 255) / 256;
    const int wgtBlocks = (NWGT / 4 + 255) / 256;

    convert_kernel<<<actBlocks, 256>>>(q,  qihi, qilo, NACT / 4);
    convert_kernel<<<actBlocks, 256>>>(k,  kihi, kilo, NACT / 4);
    convert_kernel<<<actBlocks, 256>>>(v,  vihi, vilo, NACT / 4);
    convert_kernel<<<wgtBlocks, 256>>>(wq, wqhi, wqlo, NWGT / 4);
    convert_kernel<<<wgtBlocks, 256>>>(wk, wkhi, wklo, NWGT / 4);
    convert_kernel<<<wgtBlocks, 256>>>(wv, wvhi, wvlo, NWGT / 4);
    convert_kernel<<<wgtBlocks, 256>>>(wo, wohi, wolo, NWGT / 4);

    dim3 gg(16, 64), bb(256);
    mma_gemm_kernel<<<gg, bb, gemm_smem>>>(qihi, qilo, wqhi, wqlo, bq, nullptr, qphi, qplo, 1, 0.125f);
    mma_gemm_kernel<<<gg, bb, gemm_smem>>>(kihi, kilo, wkhi, wklo, bk, nullptr, kphi, kplo, 1, 1.0f);
    mma_gemm_kernel<<<gg, bb, gemm_smem>>>(vihi, vilo, wvhi, wvlo, bv, nullptr, vphi, vplo, 1, 1.0f);

    attn_mma_kernel<<<dim3(16, 64), 256, attn_smem>>>(qphi, qplo, kphi, kplo, vphi, vplo, aohi, aolo);

    mma_gemm_kernel<<<gg, bb, gemm_smem>>>(aohi, aolo, wohi, wolo, bo, out, nullptr, nullptr, 0, 1.0f);
}